// round 13
// baseline (speedup 1.0000x reference)
#include <cuda_runtime.h>
#include <cuda_fp16.h>
#include <math.h>
#include <stdint.h>

// ---------------- problem constants ----------------
#define Bb     4
#define Nn     4096
#define Dm     1024
#define Hh     16
#define DHe    64
#define DFFe   4096
#define Mf     256
#define BH     (Bb*Hh)          // 64
#define Tt     (Bb*Nn)          // 16384
#define QKVS   3072
#define NORMF  0.3535533905932738f   // 64^-0.25
#define RATIOF 0.0625f               // 256^-0.5
#define EPSKF  1e-4f
#define LNEPS  1e-5f
#define GEMM_GRID 296

// ---------------- scratch (device globals, no allocs) ----------------
__device__ __align__(256) __half g_vidh [Tt*Dm];
__device__ __align__(256) __half g_wqkvh[3*Dm*Dm];
__device__ float  g_bqkv[3*Dm];
__device__ __align__(256) __half g_woh  [Dm*Dm];
__device__ __align__(256) __half g_w1h  [DFFe*Dm];
__device__ __align__(256) __half g_w2h  [Dm*DFFe];
__device__ __align__(256) __half g_qh  [BH*Nn*DHe];
__device__ __align__(256) __half g_kh  [BH*Nn*DHe];
__device__ __align__(256) __half g_vh  [BH*Nn*DHe];
__device__ __align__(256) __half g_projh[Mf*DHe];
__device__ __align__(256) __half g_attnh[Tt*Dm];
__device__ __align__(256) __half g_x1h [Tt*Dm];
__device__ __align__(256) __half g_ffh [Tt*DFFe];
__device__ float  g_qp  [BH*Nn*Mf];
__device__ float  g_kp  [BH*Nn*Mf];
__device__ __align__(256) __half g_qph [BH*Nn*Mf];
__device__ float  g_qdiag[BH*Nn];
__device__ float  g_kdiag[BH*Nn];
__device__ float  g_kstab[BH];
__device__ float  g_ksum[BH*Mf];
__device__ float  g_ksum_part[16*BH*Mf];
__device__ float  g_den [BH*Nn];
__device__ float  g_ctx [BH*Mf*DHe];
__device__ __align__(256) __half g_ctxTh[BH*DHe*Mf];
__device__ float  g_y   [Tt*Dm];
__device__ float  g_x1  [Tt*Dm];
__device__ float  g_zerob[Mf];

// ---------------- PTX helpers ----------------
__device__ __forceinline__ uint32_t smem_u32(const void* p){
    uint32_t a;
    asm("{ .reg .u64 t; cvta.to.shared.u64 t, %1; cvt.u32.u64 %0, t; }" : "=r"(a) : "l"(p));
    return a;
}
#define CP_ASYNC16(dst, src) \
    asm volatile("cp.async.cg.shared.global [%0], [%1], 16;" :: "r"(dst), "l"(src))
#define CP_COMMIT() asm volatile("cp.async.commit_group;" ::: "memory")
#define CP_WAIT1()  asm volatile("cp.async.wait_group 1;" ::: "memory")
#define CP_WAIT0()  asm volatile("cp.async.wait_group 0;" ::: "memory")

__device__ __forceinline__ void mma_h(float c[4], const uint32_t a[4], const uint32_t b[2]){
    asm volatile("mma.sync.aligned.m16n8k16.row.col.f32.f16.f16.f32 "
        "{%0,%1,%2,%3}, {%4,%5,%6,%7}, {%8,%9}, {%0,%1,%2,%3};"
        : "+f"(c[0]), "+f"(c[1]), "+f"(c[2]), "+f"(c[3])
        : "r"(a[0]), "r"(a[1]), "r"(a[2]), "r"(a[3]), "r"(b[0]), "r"(b[1]));
}
__device__ __forceinline__ void atomicMaxF(float* addr, float v) {
    int old = __float_as_int(*addr);
    while (__int_as_float(old) < v) {
        int assumed = old;
        old = atomicCAS((int*)addr, assumed, __float_as_int(v));
        if (old == assumed) break;
    }
}
__device__ __forceinline__ uint64_t pack2(float x){
    uint64_t r; asm("mov.b64 %0, {%1, %1};" : "=l"(r) : "f"(x)); return r;
}
__device__ __forceinline__ void ffma2(uint64_t& c, uint64_t a, uint64_t b){
    asm("fma.rn.f32x2 %0, %1, %2, %0;" : "+l"(c) : "l"(a), "l"(b));
}
__device__ __forceinline__ float2 unpack2(uint64_t v){
    float lo, hi; asm("mov.b64 {%0, %1}, %2;" : "=f"(lo), "=f"(hi) : "l"(v));
    return make_float2(lo, hi);
}

// ---------------- conversion kernels ----------------
__global__ __launch_bounds__(256)
void f2h_kernel(const float* __restrict__ src, __half* __restrict__ dst, int n4)
{
    int i = blockIdx.x*256 + threadIdx.x;
    if (i < n4) {
        float4 v = ((const float4*)src)[i];
        __half2* d = (__half2*)dst + 2*i;
        d[0] = __floats2half2_rn(v.x, v.y);
        d[1] = __floats2half2_rn(v.z, v.w);
    }
}
// merged Wo/W1/W2 conversion (float4 units: 256K + 1M + 1M)
#define WO4 (Dm*Dm/4)
#define W14 (DFFe*Dm/4)
__global__ __launch_bounds__(256)
void f2h3_kernel(const float* __restrict__ Wo, const float* __restrict__ W1,
                 const float* __restrict__ W2)
{
    int i = blockIdx.x*256 + threadIdx.x;
    const float* src; __half* dst; int off;
    if (i < WO4)            { src = Wo; dst = g_woh; off = i; }
    else if (i < WO4+W14)   { src = W1; dst = g_w1h; off = i - WO4; }
    else if (i < WO4+2*W14) { src = W2; dst = g_w2h; off = i - WO4 - W14; }
    else return;
    float4 v = ((const float4*)src)[off];
    __half2* d = (__half2*)dst + 2*off;
    d[0] = __floats2half2_rn(v.x, v.y);
    d[1] = __floats2half2_rn(v.z, v.w);
}
__global__ __launch_bounds__(256)
void pack_qkvh(const float* __restrict__ Wq, const float* __restrict__ Wk,
               const float* __restrict__ Wv, const float* __restrict__ bq,
               const float* __restrict__ bk, const float* __restrict__ bv)
{
    size_t i = (size_t)blockIdx.x*256 + threadIdx.x;
    if (i < (size_t)3*Dm*Dm) {
        int seg = (int)(i >> 20);
        size_t off = i & 0xFFFFF;
        const float* s = (seg == 0) ? Wq : (seg == 1) ? Wk : Wv;
        g_wqkvh[i] = __float2half_rn(s[off]);
    }
    if (i < 3*Dm)
        g_bqkv[i] = (i < Dm) ? bq[i] : (i < 2*Dm) ? bk[i-Dm] : bv[i-2*Dm];
}
__global__ __launch_bounds__(256)
void pack_projh(const float* __restrict__ proj)
{
    int i = blockIdx.x*256 + threadIdx.x;
    if (i < Mf*DHe) g_projh[i] = __float2half_rn(proj[i] * NORMF);
}

// ---------------- fp16 mma GEMM-NT, persistent tiles (R11 structure) -------
// BM=256, BN=128, BK=64. 8 warps (4Mx2N). Per-tile 2-stage cp.async.
// mode 0: plain (Cf or Ch). mode 1: QKV -> qh/kh/vh head-major half + diag.
// mode 2: feat-k (fp32 C + per-tile warp atomicMax into g_kstab[bz]).
#define HSTR    72
#define HA_BY   (256*HSTR*2)
#define HB_BY   (128*HSTR*2)
#define HSTAGE  (HA_BY+HB_BY)
#define HSMEM   (2*HSTAGE)       // 110592

__global__ __launch_bounds__(256)
void hgemm(const __half* __restrict__ A, const __half* __restrict__ W,
           const float* __restrict__ bias, float* __restrict__ Cf,
           __half* __restrict__ Ch, int M, int N, int K, int relu,
           int mode, size_t zsA, size_t zsC, int tiles, int gx, int gy)
{
    extern __shared__ char smc[];
    const uint32_t sb = smem_u32(smc);
    const int tid  = threadIdx.x;
    const int lane = tid & 31;
    const int w    = tid >> 5;
    const int wm   = (w & 3) * 64;
    const int wn   = (w >> 2) * 64;
    const int lr   = lane >> 2;
    const int lc   = lane & 3;
    const int r8 = tid >> 3, cc8 = tid & 7;
    const int KT = K / 64;

    for (int t = blockIdx.x; t < tiles; t += gridDim.x) {
        const int bx = t % gx;
        const int rr = t / gx;
        const int by = rr % gy;
        const int bz = rr / gy;

        const __half* At = A + (size_t)bz * zsA;
        float* Cft = Cf ? Cf + (size_t)bz * zsC : (float*)0;
        __half* Cht = Ch ? Ch + (size_t)bz * zsC : (__half*)0;

        const int blockM = by * 256;
        const int blockN = bx * 128;

        float c[4][8][4];
        #pragma unroll
        for (int i = 0; i < 4; i++)
            #pragma unroll
            for (int j = 0; j < 8; j++)
                #pragma unroll
                for (int tt = 0; tt < 4; tt++) c[i][j][tt] = 0.f;

        const __half* Abase = At + (size_t)blockM * K;
        const __half* Wbase = W + (size_t)blockN * K;

        auto issue = [&](int kt) {
            const int buf = kt & 1;
            const uint32_t dA = sb + buf*HSTAGE;
            const uint32_t dB = dA + HA_BY;
            const __half* As = Abase + kt*64;
            const __half* Ws = Wbase + kt*64;
            #pragma unroll
            for (int it = 0; it < 8; it++) {
                int r = r8 + it*32;
                CP_ASYNC16(dA + r*(HSTR*2) + cc8*16, As + (size_t)r*K + cc8*8);
            }
            #pragma unroll
            for (int it = 0; it < 4; it++) {
                int r = r8 + it*32;
                CP_ASYNC16(dB + r*(HSTR*2) + cc8*16, Ws + (size_t)r*K + cc8*8);
            }
        };

        issue(0); CP_COMMIT();
        if (KT > 1) { issue(1); CP_COMMIT(); CP_WAIT1(); }
        else        { CP_WAIT0(); }
        __syncthreads();

        for (int kt = 0; kt < KT; kt++) {
            const char* bufA = smc + (kt & 1)*HSTAGE;
            const char* bufB = bufA + HA_BY;

            #pragma unroll
            for (int ks = 0; ks < 4; ks++) {
                const int k0 = ks*16;
                uint32_t a[4][4], b[8][2];
                #pragma unroll
                for (int i = 0; i < 4; i++) {
                    int r = wm + i*16 + lr;
                    const char* p = bufA + (r*HSTR + k0 + lc*2)*2;
                    a[i][0] = *(const uint32_t*)(p);
                    a[i][1] = *(const uint32_t*)(p + 8*HSTR*2);
                    a[i][2] = *(const uint32_t*)(p + 16);
                    a[i][3] = *(const uint32_t*)(p + 8*HSTR*2 + 16);
                }
                #pragma unroll
                for (int j = 0; j < 8; j++) {
                    int n = wn + j*8 + lr;
                    const char* p = bufB + (n*HSTR + k0 + lc*2)*2;
                    b[j][0] = *(const uint32_t*)(p);
                    b[j][1] = *(const uint32_t*)(p + 16);
                }
                #pragma unroll
                for (int i = 0; i < 4; i++)
                    #pragma unroll
                    for (int j = 0; j < 8; j++)
                        mma_h(c[i][j], a[i], b[j]);
            }
            __syncthreads();
            if (kt + 2 < KT) {
                issue(kt + 2); CP_COMMIT();
                CP_WAIT1(); __syncthreads();
            } else if (kt + 1 < KT) {
                CP_WAIT0(); __syncthreads();
            }
        }
        __syncthreads();   // protect smem before next tile's prologue

        // ---- epilogue ----
        int seg = 3, hh = 0;
        if (mode == 1) { int slot = (blockN + wn) >> 6; seg = slot >> 4; hh = slot & 15; }
        float wmax = -INFINITY;

        #pragma unroll
        for (int i = 0; i < 4; i++) {
            int gr = blockM + wm + i*16 + lr;
            float ds0 = 0.f, ds1 = 0.f;
            #pragma unroll
            for (int j = 0; j < 8; j++) {
                int gc = blockN + wn + j*8 + 2*lc;
                float b0 = bias[gc], b1 = bias[gc+1];
                float o0 = c[i][j][0] + b0, o1 = c[i][j][1] + b1;
                float o2 = c[i][j][2] + b0, o3 = c[i][j][3] + b1;
                if (relu) {
                    o0 = fmaxf(o0, 0.f); o1 = fmaxf(o1, 0.f);
                    o2 = fmaxf(o2, 0.f); o3 = fmaxf(o3, 0.f);
                }
                if (mode == 2)
                    wmax = fmaxf(wmax, fmaxf(fmaxf(o0, o1), fmaxf(o2, o3)));
                if (mode == 1) {
                    int d = gc & 63, bb = gr >> 12, nn = gr & 4095;
                    size_t hidx = ((size_t)((bb<<4) + hh)*4096 + nn)*64 + d;
                    __half* dst = (seg == 0) ? g_qh : (seg == 1) ? g_kh : g_vh;
                    *(__half2*)(dst + hidx)        = __floats2half2_rn(o0, o1);
                    *(__half2*)(dst + hidx + 8*64) = __floats2half2_rn(o2, o3);
                    if (seg < 2) {
                        ds0 += o0*o0 + o1*o1;
                        ds1 += o2*o2 + o3*o3;
                    }
                } else if (Cft) {
                    *(float2*)(Cft + (size_t)gr*N + gc)     = make_float2(o0, o1);
                    *(float2*)(Cft + (size_t)(gr+8)*N + gc) = make_float2(o2, o3);
                } else {
                    *(__half2*)(Cht + (size_t)gr*N + gc)     = __floats2half2_rn(o0, o1);
                    *(__half2*)(Cht + (size_t)(gr+8)*N + gc) = __floats2half2_rn(o2, o3);
                }
            }
            if (mode == 1 && seg < 2) {
                ds0 += __shfl_xor_sync(0xffffffffu, ds0, 1);
                ds0 += __shfl_xor_sync(0xffffffffu, ds0, 2);
                ds1 += __shfl_xor_sync(0xffffffffu, ds1, 1);
                ds1 += __shfl_xor_sync(0xffffffffu, ds1, 2);
                if (lc == 0) {
                    int bb = gr >> 12, nn = gr & 4095;
                    size_t r0 = (size_t)((bb<<4) + hh)*4096 + nn;
                    float* dd = (seg == 0) ? g_qdiag : g_kdiag;
                    dd[r0]     = 0.0625f * ds0;
                    dd[r0 + 8] = 0.0625f * ds1;
                }
            }
        }
        if (mode == 2) {
            #pragma unroll
            for (int off = 16; off; off >>= 1)
                wmax = fmaxf(wmax, __shfl_xor_sync(0xffffffffu, wmax, off));
            if (lane == 0) atomicMaxF(&g_kstab[bz], wmax);
        }
    }
}

// ---------------- attnout GEMM: per head M=4096 N=64 K=256 ----------------
#define N64_HA  (256*HSTR*2)
#define N64_HB  (64*HSTR*2)
#define N64_ST  (N64_HA+N64_HB)
#define N64SMEM (2*N64_ST)

__global__ __launch_bounds__(256)
void hgemm_n64()
{
    extern __shared__ char smc[];
    const uint32_t sb = smem_u32(smc);
    const int tid  = threadIdx.x;
    const int lane = tid & 31;
    const int w    = tid >> 5;
    const int wm   = (w & 3) * 64;
    const int wn   = (w >> 2) * 32;
    const int lr   = lane >> 2;
    const int lc   = lane & 3;

    const int bh     = blockIdx.y;
    const int blockM = blockIdx.x * 256;
    const __half* A = g_qph  + (size_t)bh*Nn*Mf + (size_t)blockM*Mf;
    const __half* B = g_ctxTh + (size_t)bh*DHe*Mf;

    float c[4][4][4];
    #pragma unroll
    for (int i = 0; i < 4; i++)
        #pragma unroll
        for (int j = 0; j < 4; j++)
            #pragma unroll
            for (int t = 0; t < 4; t++) c[i][j][t] = 0.f;

    const int r8 = tid >> 3, cc8 = tid & 7;

    auto issue = [&](int kt) {
        const int buf = kt & 1;
        const uint32_t dA = sb + buf*N64_ST;
        const uint32_t dB = dA + N64_HA;
        const __half* As = A + kt*64;
        const __half* Bs = B + kt*64;
        #pragma unroll
        for (int it = 0; it < 8; it++) {
            int r = r8 + it*32;
            CP_ASYNC16(dA + r*(HSTR*2) + cc8*16, As + (size_t)r*Mf + cc8*8);
        }
        #pragma unroll
        for (int it = 0; it < 2; it++) {
            int r = r8 + it*32;
            CP_ASYNC16(dB + r*(HSTR*2) + cc8*16, Bs + (size_t)r*Mf + cc8*8);
        }
    };

    issue(0); CP_COMMIT();
    issue(1); CP_COMMIT();
    CP_WAIT1(); __syncthreads();

    const int KT = Mf/64;   // 4
    for (int kt = 0; kt < KT; kt++) {
        const char* bufA = smc + (kt & 1)*N64_ST;
        const char* bufB = bufA + N64_HA;

        #pragma unroll
        for (int ks = 0; ks < 4; ks++) {
            const int k0 = ks*16;
            uint32_t a[4][4], b[4][2];
            #pragma unroll
            for (int i = 0; i < 4; i++) {
                int r = wm + i*16 + lr;
                const char* p = bufA + (r*HSTR + k0 + lc*2)*2;
                a[i][0] = *(const uint32_t*)(p);
                a[i][1] = *(const uint32_t*)(p + 8*HSTR*2);
                a[i][2] = *(const uint32_t*)(p + 16);
                a[i][3] = *(const uint32_t*)(p + 8*HSTR*2 + 16);
            }
            #pragma unroll
            for (int j = 0; j < 4; j++) {
                int n = wn + j*8 + lr;
                const char* p = bufB + (n*HSTR + k0 + lc*2)*2;
                b[j][0] = *(const uint32_t*)(p);
                b[j][1] = *(const uint32_t*)(p + 16);
            }
            #pragma unroll
            for (int i = 0; i < 4; i++)
                #pragma unroll
                for (int j = 0; j < 4; j++)
                    mma_h(c[i][j], a[i], b[j]);
        }
        __syncthreads();
        if (kt + 2 < KT) {
            issue(kt + 2); CP_COMMIT();
            CP_WAIT1(); __syncthreads();
        } else if (kt + 1 < KT) {
            CP_WAIT0(); __syncthreads();
        }
    }

    const int bb = bh >> 4, h = bh & 15;
    #pragma unroll
    for (int i = 0; i < 4; i++) {
        int n0 = blockM + wm + i*16 + lr;
        float rd0 = 1.f / g_den[bh*Nn + n0];
        float rd1 = 1.f / g_den[bh*Nn + n0 + 8];
        size_t t0 = ((size_t)bb*Nn + n0)*Dm + h*64;
        size_t t1 = t0 + (size_t)8*Dm;
        #pragma unroll
        for (int j = 0; j < 4; j++) {
            int d = wn + j*8 + 2*lc;
            *(__half2*)(g_attnh + t0 + d) = __floats2half2_rn(c[i][j][0]*rd0, c[i][j][1]*rd0);
            *(__half2*)(g_attnh + t1 + d) = __floats2half2_rn(c[i][j][2]*rd1, c[i][j][3]*rd1);
        }
    }
}

// ---------------- init kstab ----------------
__global__ void init_kstab() {
    if (threadIdx.x < BH) g_kstab[threadIdx.x] = -INFINITY;
}

// ---------------- qexp ----------------
__global__ __launch_bounds__(256)
void qexp_kernel()
{
    const int row = blockIdx.x*8 + (threadIdx.x >> 5);
    const int lane = threadIdx.x & 31;
    const float4* xp4 = (const float4*)(g_qp + (size_t)row*Mf);
    float4 v0 = xp4[lane], v1 = xp4[lane+32];
    float mx = fmaxf(fmaxf(fmaxf(v0.x,v0.y),fmaxf(v0.z,v0.w)),
                     fmaxf(fmaxf(v1.x,v1.y),fmaxf(v1.z,v1.w)));
    #pragma unroll
    for (int off = 16; off; off >>= 1)
        mx = fmaxf(mx, __shfl_xor_sync(0xffffffffu, mx, off));
    float sh = g_qdiag[row] + mx;
    __half2* o = (__half2*)(g_qph + (size_t)row*Mf);
    o[2*lane]      = __floats2half2_rn(__expf(v0.x-sh)+EPSKF, __expf(v0.y-sh)+EPSKF);
    o[2*lane+1]    = __floats2half2_rn(__expf(v0.z-sh)+EPSKF, __expf(v0.w-sh)+EPSKF);
    o[2*lane+64]   = __floats2half2_rn(__expf(v1.x-sh)+EPSKF, __expf(v1.y-sh)+EPSKF);
    o[2*lane+65]   = __floats2half2_rn(__expf(v1.z-sh)+EPSKF, __expf(v1.w-sh)+EPSKF);
}

// ---------------- fused kexp + ksum partials ----------------
__global__ __launch_bounds__(256)
void kexp_ksum_kernel()
{
    const int bh = blockIdx.x;
    const int part = blockIdx.y;
    const int m = threadIdx.x;
    const float stab = g_kstab[bh];
    const int row0 = bh*Nn + part*256;
    float* kp = g_kp + (size_t)bh * Nn * Mf + (size_t)part * 256 * Mf + m;
    float acc = 0.f;
    #pragma unroll 4
    for (int n = 0; n < 256; n++) {
        float xp = kp[(size_t)n * Mf];
        float kv = RATIOF * (__expf(xp - g_kdiag[row0 + n] - stab) + EPSKF);
        kp[(size_t)n * Mf] = kv;
        acc += kv;
    }
    g_ksum_part[(part*BH + bh)*Mf + m] = acc;
}
__global__ __launch_bounds__(256)
void ksum_reduce_kernel()
{
    const int bh = blockIdx.x;
    const int m = threadIdx.x;
    float acc = 0.f;
    #pragma unroll
    for (int p = 0; p < 16; p++) acc += g_ksum_part[(p*BH + bh)*Mf + m];
    g_ksum[bh*Mf + m] = acc;
}

// ---------------- den ----------------
__global__ __launch_bounds__(256)
void den_kernel()
{
    const int row = blockIdx.x*8 + (threadIdx.x >> 5);
    const int lane = threadIdx.x & 31;
    const int bh = row >> 12;
    uint4 qv = ((const uint4*)(g_qph + (size_t)row*Mf))[lane];
    const float4* ks4 = (const float4*)(g_ksum + bh*Mf);
    float4 k0 = ks4[2*lane], k1 = ks4[2*lane+1];
    float2 q0 = __half22float2(*(__half2*)&qv.x);
    float2 q1 = __half22float2(*(((__half2*)&qv.x)+1));
    float2 q2 = __half22float2(*(__half2*)&qv.z);
    float2 q3 = __half22float2(*(((__half2*)&qv.z)+1));
    float s = q0.x*k0.x + q0.y*k0.y + q1.x*k0.z + q1.y*k0.w
            + q2.x*k1.x + q2.y*k1.y + q3.x*k1.z + q3.y*k1.w;
    #pragma unroll
    for (int off = 16; off; off >>= 1) s += __shfl_xor_sync(0xffffffffu, s, off);
    if (lane == 0) g_den[row] = s;
}

// ---------------- ctx (packed f32x2 FFMA2, half v head-major) ------------
__global__ __launch_bounds__(256)
void ctx_kernel()
{
    __shared__ float kpc[32][64];
    __shared__ float vc [32][64];

    const int bh = blockIdx.x;
    const int mtile = blockIdx.y;
    const int tid = threadIdx.x;
    const int tx = tid & 15;
    const int ty = tid >> 4;

    uint64_t acc2[4][2];
    const uint64_t z2 = pack2(0.f);
    #pragma unroll
    for (int i = 0; i < 4; i++) { acc2[i][0] = z2; acc2[i][1] = z2; }

    const float* kpBase = g_kp + (size_t)bh * Nn * Mf + mtile*64;
    const __half* vBase = g_vh + (size_t)bh * Nn * DHe;

    for (int n0 = 0; n0 < Nn; n0 += 32) {
        #pragma unroll
        for (int it = 0; it < 8; it++) {
            int j = it*256 + tid;
            int nn = j >> 6, cq = j & 63;
            kpc[nn][cq] = kpBase[(size_t)(n0+nn)*Mf + cq];
            vc [nn][cq] = __half2float(vBase[(size_t)(n0+nn)*DHe + cq]);
        }
        __syncthreads();
        #pragma unroll
        for (int nn = 0; nn < 32; nn++) {
            float4 kf = *(const float4*)&kpc[nn][ty*4];
            float4 vf = *(const float4*)&vc [nn][tx*4];
            uint64_t v01, v23;
            asm("mov.b64 %0, {%1, %2};" : "=l"(v01) : "f"(vf.x), "f"(vf.y));
            asm("mov.b64 %0, {%1, %2};" : "=l"(v23) : "f"(vf.z), "f"(vf.w));
            float kr[4] = {kf.x,kf.y,kf.z,kf.w};
            #pragma unroll
            for (int i = 0; i < 4; i++) {
                uint64_t kk = pack2(kr[i]);
                ffma2(acc2[i][0], kk, v01);
                ffma2(acc2[i][1], kk, v23);
            }
        }
        __syncthreads();
    }
    #pragma unroll
    for (int i = 0; i < 4; i++) {
        int m = mtile*64 + ty*4 + i;
        float2 lo = unpack2(acc2[i][0]);
        float2 hi = unpack2(acc2[i][1]);
        float* cp = g_ctx + (size_t)bh*Mf*DHe + m*DHe + tx*4;
        *(float4*)cp = make_float4(lo.x, lo.y, hi.x, hi.y);
    }
}

// ---------------- ctx -> ctxT half ----------------
__global__ __launch_bounds__(256)
void ctxT_kernel()
{
    const int bh = blockIdx.x;
    const float* src = g_ctx + (size_t)bh*Mf*DHe;
    __half* dst = g_ctxTh + (size_t)bh*DHe*Mf;
    for (int i = threadIdx.x; i < Mf*DHe; i += 256) {
        int m = i >> 6, d = i & 63;
        dst[d*Mf + m] = __float2half_rn(src[i]);
    }
}

// ---------------- LayerNorm(a + b) * g + be ----------------
__global__ __launch_bounds__(256)
void ln_kernel(const float* __restrict__ A, const float* __restrict__ Bc,
               const float* __restrict__ g, const float* __restrict__ be,
               float* __restrict__ outf, __half* __restrict__ outh)
{
    __shared__ float s1s[8], s2s[8], bc[2];
    const int row = blockIdx.x;
    const int tid = threadIdx.x;
    const int lane = tid & 31, wid = tid >> 5;

    const float4* a4 = (const float4*)(A  + (size_t)row*Dm);
    const float4* b4 = (const float4*)(Bc + (size_t)row*Dm);
    float4 va = a4[tid], vb = b4[tid];
    float4 v = make_float4(va.x+vb.x, va.y+vb.y, va.z+vb.z, va.w+vb.w);

    float s1 = v.x+v.y+v.z+v.w;
    float s2 = v.x*v.x+v.y*v.y+v.z*v.z+v.w*v.w;
    #pragma unroll
    for (int off = 16; off; off >>= 1) {
        s1 += __shfl_xor_sync(0xffffffffu, s1, off);
        s2 += __shfl_xor_sync(0xffffffffu, s2, off);
    }
    if (lane == 0) { s1s[wid] = s1; s2s[wid] = s2; }
    __syncthreads();
    if (tid == 0) {
        float S1 = 0.f, S2 = 0.f;
        #pragma unroll
        for (int i = 0; i < 8; i++) { S1 += s1s[i]; S2 += s2s[i]; }
        float mu = S1 * (1.f/Dm);
        float var = S2 * (1.f/Dm) - mu*mu;
        bc[0] = mu;
        bc[1] = rsqrtf(var + LNEPS);
    }
    __syncthreads();
    float mu = bc[0], rstd = bc[1];

    float4 gg = ((const float4*)g)[tid];
    float4 bb = ((const float4*)be)[tid];
    float4 o = make_float4((v.x-mu)*rstd*gg.x + bb.x,
                           (v.y-mu)*rstd*gg.y + bb.y,
                           (v.z-mu)*rstd*gg.z + bb.z,
                           (v.w-mu)*rstd*gg.w + bb.w);
    ((float4*)(outf + (size_t)row*Dm))[tid] = o;
    if (outh) {
        __half2* oh = (__half2*)(outh + (size_t)row*Dm) + 2*tid;
        oh[0] = __floats2half2_rn(o.x, o.y);
        oh[1] = __floats2half2_rn(o.z, o.w);
    }
}

// ---------------- host ----------------
static inline void launch_hgemm(const __half* A, const __half* W, const float* bias,
                                float* Cf, __half* Ch, int M, int N, int K, int relu,
                                int mode, size_t zsA, size_t zsC, int gz)
{
    int gx = N / 128, gy = M / 256;
    int tiles = gx * gy * gz;
    int grid = tiles < GEMM_GRID ? tiles : GEMM_GRID;
    hgemm<<<grid, 256, HSMEM>>>(A, W, bias, Cf, Ch, M, N, K, relu, mode, zsA, zsC,
                                tiles, gx, gy);
}

extern "C" void kernel_launch(void* const* d_in, const int* in_sizes, int n_in,
                              void* d_out, int out_size)
{
    const float* video = (const float*)d_in[0];
    const float* Wq    = (const float*)d_in[1];
    const float* bq    = (const float*)d_in[2];
    const float* Wk    = (const float*)d_in[3];
    const float* bk    = (const float*)d_in[4];
    const float* Wv    = (const float*)d_in[5];
    const float* bv    = (const float*)d_in[6];
    const float* Wo    = (const float*)d_in[7];
    const float* bo    = (const float*)d_in[8];
    const float* proj  = (const float*)d_in[9];
    const float* W1    = (const float*)d_in[10];
    const float* b1    = (const float*)d_in[11];
    const float* W2    = (const float*)d_in[12];
    const float* b2    = (const float*)d_in[13];
    const float* g2    = (const float*)d_in[14];
    const float* be2   = (const float*)d_in[15];
    const float* g3    = (const float*)d_in[16];
    const float* be3   = (const float*)d_in[17];
    float* out = (float*)d_out;

    __half *vidh, *wqkvh, *woh, *w1h, *w2h, *attnh, *x1h, *ffh, *qh, *kh, *projh;
    float *bqkv, *y, *x1, *qp, *kp, *zerob;
    cudaGetSymbolAddress((void**)&vidh,  g_vidh);
    cudaGetSymbolAddress((void**)&wqkvh, g_wqkvh);
    cudaGetSymbolAddress((void**)&bqkv,  g_bqkv);
    cudaGetSymbolAddress((void**)&woh,   g_woh);
    cudaGetSymbolAddress((void**)&w1h,   g_w1h);
    cudaGetSymbolAddress((void**)&w2h,   g_w2h);
    cudaGetSymbolAddress((void**)&attnh, g_attnh);
    cudaGetSymbolAddress((void**)&x1h,   g_x1h);
    cudaGetSymbolAddress((void**)&ffh,   g_ffh);
    cudaGetSymbolAddress((void**)&y,     g_y);
    cudaGetSymbolAddress((void**)&x1,    g_x1);
    cudaGetSymbolAddress((void**)&qh,    g_qh);
    cudaGetSymbolAddress((void**)&kh,    g_kh);
    cudaGetSymbolAddress((void**)&projh, g_projh);
    cudaGetSymbolAddress((void**)&qp,    g_qp);
    cudaGetSymbolAddress((void**)&kp,    g_kp);
    cudaGetSymbolAddress((void**)&zerob, g_zerob);

    cudaFuncSetAttribute(hgemm,     cudaFuncAttributeMaxDynamicSharedMemorySize, HSMEM);
    cudaFuncSetAttribute(hgemm_n64, cudaFuncAttributeMaxDynamicSharedMemorySize, N64SMEM);

    // 0. conversions
    pack_qkvh<<<(3*Dm*Dm + 255)/256, 256>>>(Wq, Wk, Wv, bq, bk, bv);
    pack_projh<<<(Mf*DHe + 255)/256, 256>>>(proj);
    f2h_kernel<<<(Tt*Dm/4 + 255)/256, 256>>>(video, vidh, Tt*Dm/4);
    f2h3_kernel<<<(WO4 + 2*W14 + 255)/256, 256>>>(Wo, W1, W2);
    init_kstab<<<1, 64>>>();

    // 1. fused QKV projection (mode 1: qh/kh/vh head-major half + diag)
    launch_hgemm(vidh, wqkvh, bqkv, nullptr, nullptr, Tt, QKVS, Dm, 0, 1, 0, 0, 1);

    // 2. feature-map GEMMs (batched per head); feat-k fuses kstab max (mode 2)
    launch_hgemm(qh, projh, zerob, qp, nullptr, Nn, Mf, DHe, 0, 0,
                 (size_t)Nn*DHe, (size_t)Nn*Mf, BH);
    launch_hgemm(kh, projh, zerob, kp, nullptr, Nn, Mf, DHe, 0, 2,
                 (size_t)Nn*DHe, (size_t)Nn*Mf, BH);

    // 3. exps (k exp fused with ksum partials)
    qexp_kernel<<<(BH*Nn)/8, 256>>>();
    kexp_ksum_kernel<<<dim3(BH, 16), 256>>>();
    ksum_reduce_kernel<<<BH, 256>>>();

    // 4. linear attention
    den_kernel<<<(BH*Nn)/8, 256>>>();
    ctx_kernel<<<dim3(BH, Mf/64), 256>>>();
    ctxT_kernel<<<BH, 256>>>();
    hgemm_n64<<<dim3(Nn/256, BH), 256, N64SMEM>>>();

    // 5. output projection + residual LN
    launch_hgemm(attnh, woh, bo, y, nullptr, Tt, Dm, Dm, 0, 0, 0, 0, 1);
    ln_kernel<<<Tt, 256>>>(video, y, g2, be2, x1, x1h);

    // 6. FFN
    launch_hgemm(x1h, w1h, b1, nullptr, ffh, Tt, DFFe, Dm, 1, 0, 0, 0, 1);
    launch_hgemm(ffh, w2h, b2, y, nullptr, Tt, Dm, DFFe, 0, 0, 0, 0, 1);
    ln_kernel<<<Tt, 256>>>(x1, y, g3, be3, out, nullptr);
}

// round 14
// speedup vs baseline: 1.4712x; 1.4712x over previous
#include <cuda_runtime.h>
#include <cuda_fp16.h>
#include <math.h>
#include <stdint.h>

// ---------------- problem constants ----------------
#define Bb     4
#define Nn     4096
#define Dm     1024
#define Hh     16
#define DHe    64
#define DFFe   4096
#define Mf     256
#define BH     (Bb*Hh)          // 64
#define Tt     (Bb*Nn)          // 16384
#define QKVS   3072
#define NORMF  0.3535533905932738f   // 64^-0.25
#define RATIOF 0.0625f               // 256^-0.5
#define EPSKF  1e-4f
#define LNEPS  1e-5f
#define GEMM_GRID 296

// ---------------- scratch (device globals, no allocs) ----------------
__device__ __align__(256) __half g_vidh [Tt*Dm];
__device__ __align__(256) __half g_wqkvh[3*Dm*Dm];
__device__ float  g_bqkv[3*Dm];
__device__ __align__(256) __half g_woh  [Dm*Dm];
__device__ __align__(256) __half g_w1h  [DFFe*Dm];
__device__ __align__(256) __half g_w2h  [Dm*DFFe];
__device__ float  g_qkv [Tt*QKVS];    // fused q|k|v fp32 (v slice used by ctx)
__device__ __align__(256) __half g_qh  [BH*Nn*DHe];
__device__ __align__(256) __half g_kh  [BH*Nn*DHe];
__device__ __align__(256) __half g_projh[Mf*DHe];
__device__ __align__(256) __half g_attnh[Tt*Dm];
__device__ __align__(256) __half g_x1h [Tt*Dm];
__device__ __align__(256) __half g_ffh [Tt*DFFe];
__device__ float  g_qp  [BH*Nn*Mf];
__device__ float  g_kp  [BH*Nn*Mf];
__device__ __align__(256) __half g_qph [BH*Nn*Mf];
__device__ float  g_qdiag[BH*Nn];
__device__ float  g_kdiag[BH*Nn];
__device__ float  g_kstab[BH];
__device__ float  g_ksum[BH*Mf];
__device__ float  g_ksum_part[16*BH*Mf];
__device__ float  g_den [BH*Nn];
__device__ __align__(256) __half g_ctxTh[BH*DHe*Mf];  // ctx^T half [bh][d][m]
__device__ float  g_y   [Tt*Dm];
__device__ float  g_x1  [Tt*Dm];
__device__ float  g_zerob[Mf];

// ---------------- PTX helpers ----------------
__device__ __forceinline__ uint32_t smem_u32(const void* p){
    uint32_t a;
    asm("{ .reg .u64 t; cvta.to.shared.u64 t, %1; cvt.u32.u64 %0, t; }" : "=r"(a) : "l"(p));
    return a;
}
#define CP_ASYNC16(dst, src) \
    asm volatile("cp.async.cg.shared.global [%0], [%1], 16;" :: "r"(dst), "l"(src))
#define CP_COMMIT() asm volatile("cp.async.commit_group;" ::: "memory")
#define CP_WAIT1()  asm volatile("cp.async.wait_group 1;" ::: "memory")
#define CP_WAIT0()  asm volatile("cp.async.wait_group 0;" ::: "memory")

__device__ __forceinline__ void mma_h(float c[4], const uint32_t a[4], const uint32_t b[2]){
    asm volatile("mma.sync.aligned.m16n8k16.row.col.f32.f16.f16.f32 "
        "{%0,%1,%2,%3}, {%4,%5,%6,%7}, {%8,%9}, {%0,%1,%2,%3};"
        : "+f"(c[0]), "+f"(c[1]), "+f"(c[2]), "+f"(c[3])
        : "r"(a[0]), "r"(a[1]), "r"(a[2]), "r"(a[3]), "r"(b[0]), "r"(b[1]));
}
__device__ __forceinline__ void atomicMaxF(float* addr, float v) {
    int old = __float_as_int(*addr);
    while (__int_as_float(old) < v) {
        int assumed = old;
        old = atomicCAS((int*)addr, assumed, __float_as_int(v));
        if (old == assumed) break;
    }
}
__device__ __forceinline__ uint64_t pack2(float x){
    uint64_t r; asm("mov.b64 %0, {%1, %1};" : "=l"(r) : "f"(x)); return r;
}
__device__ __forceinline__ void ffma2(uint64_t& c, uint64_t a, uint64_t b){
    asm("fma.rn.f32x2 %0, %1, %2, %0;" : "+l"(c) : "l"(a), "l"(b));
}
__device__ __forceinline__ float2 unpack2(uint64_t v){
    float lo, hi; asm("mov.b64 {%0, %1}, %2;" : "=f"(lo), "=f"(hi) : "l"(v));
    return make_float2(lo, hi);
}

// ---------------- conversion kernels ----------------
__global__ __launch_bounds__(256)
void f2h_kernel(const float* __restrict__ src, __half* __restrict__ dst, int n4)
{
    int i = blockIdx.x*256 + threadIdx.x;
    if (i < n4) {
        float4 v = ((const float4*)src)[i];
        __half2* d = (__half2*)dst + 2*i;
        d[0] = __floats2half2_rn(v.x, v.y);
        d[1] = __floats2half2_rn(v.z, v.w);
    }
}
__global__ __launch_bounds__(256)
void pack_qkvh(const float* __restrict__ Wq, const float* __restrict__ Wk,
               const float* __restrict__ Wv, const float* __restrict__ bq,
               const float* __restrict__ bk, const float* __restrict__ bv)
{
    size_t i = (size_t)blockIdx.x*256 + threadIdx.x;
    if (i < (size_t)3*Dm*Dm) {
        int seg = (int)(i >> 20);
        size_t off = i & 0xFFFFF;
        const float* s = (seg == 0) ? Wq : (seg == 1) ? Wk : Wv;
        g_wqkvh[i] = __float2half_rn(s[off]);
    }
    if (i < 3*Dm)
        g_bqkv[i] = (i < Dm) ? bq[i] : (i < 2*Dm) ? bk[i-Dm] : bv[i-2*Dm];
}
__global__ __launch_bounds__(256)
void pack_projh(const float* __restrict__ proj)
{
    int i = blockIdx.x*256 + threadIdx.x;
    if (i < Mf*DHe) g_projh[i] = __float2half_rn(proj[i] * NORMF);
}

// ---------------- fp16 mma GEMM-NT, persistent tiles (R11 exact) -----------
#define HSTR    72
#define HA_BY   (256*HSTR*2)
#define HB_BY   (128*HSTR*2)
#define HSTAGE  (HA_BY+HB_BY)
#define HSMEM   (2*HSTAGE)       // 110592

__global__ __launch_bounds__(256)
void hgemm(const __half* __restrict__ A, const __half* __restrict__ W,
           const float* __restrict__ bias, float* __restrict__ Cf,
           __half* __restrict__ Ch, int M, int N, int K, int relu,
           int mode, size_t zsA, size_t zsC, int tiles, int gx, int gy)
{
    extern __shared__ char smc[];
    const uint32_t sb = smem_u32(smc);
    const int tid  = threadIdx.x;
    const int lane = tid & 31;
    const int w    = tid >> 5;
    const int wm   = (w & 3) * 64;
    const int wn   = (w >> 2) * 64;
    const int lr   = lane >> 2;
    const int lc   = lane & 3;
    const int r8 = tid >> 3, cc8 = tid & 7;
    const int KT = K / 64;

    for (int t = blockIdx.x; t < tiles; t += gridDim.x) {
        const int bx = t % gx;
        const int rr = t / gx;
        const int by = rr % gy;
        const int bz = rr / gy;

        const __half* At = A + (size_t)bz * zsA;
        float* Cft = Cf ? Cf + (size_t)bz * zsC : (float*)0;
        __half* Cht = Ch ? Ch + (size_t)bz * zsC : (__half*)0;

        const int blockM = by * 256;
        const int blockN = bx * 128;

        float c[4][8][4];
        #pragma unroll
        for (int i = 0; i < 4; i++)
            #pragma unroll
            for (int j = 0; j < 8; j++)
                #pragma unroll
                for (int tt = 0; tt < 4; tt++) c[i][j][tt] = 0.f;

        const __half* Abase = At + (size_t)blockM * K;
        const __half* Wbase = W + (size_t)blockN * K;

        auto issue = [&](int kt) {
            const int buf = kt & 1;
            const uint32_t dA = sb + buf*HSTAGE;
            const uint32_t dB = dA + HA_BY;
            const __half* As = Abase + kt*64;
            const __half* Ws = Wbase + kt*64;
            #pragma unroll
            for (int it = 0; it < 8; it++) {
                int r = r8 + it*32;
                CP_ASYNC16(dA + r*(HSTR*2) + cc8*16, As + (size_t)r*K + cc8*8);
            }
            #pragma unroll
            for (int it = 0; it < 4; it++) {
                int r = r8 + it*32;
                CP_ASYNC16(dB + r*(HSTR*2) + cc8*16, Ws + (size_t)r*K + cc8*8);
            }
        };

        issue(0); CP_COMMIT();
        if (KT > 1) { issue(1); CP_COMMIT(); CP_WAIT1(); }
        else        { CP_WAIT0(); }
        __syncthreads();

        for (int kt = 0; kt < KT; kt++) {
            const char* bufA = smc + (kt & 1)*HSTAGE;
            const char* bufB = bufA + HA_BY;

            #pragma unroll
            for (int ks = 0; ks < 4; ks++) {
                const int k0 = ks*16;
                uint32_t a[4][4], b[8][2];
                #pragma unroll
                for (int i = 0; i < 4; i++) {
                    int r = wm + i*16 + lr;
                    const char* p = bufA + (r*HSTR + k0 + lc*2)*2;
                    a[i][0] = *(const uint32_t*)(p);
                    a[i][1] = *(const uint32_t*)(p + 8*HSTR*2);
                    a[i][2] = *(const uint32_t*)(p + 16);
                    a[i][3] = *(const uint32_t*)(p + 8*HSTR*2 + 16);
                }
                #pragma unroll
                for (int j = 0; j < 8; j++) {
                    int n = wn + j*8 + lr;
                    const char* p = bufB + (n*HSTR + k0 + lc*2)*2;
                    b[j][0] = *(const uint32_t*)(p);
                    b[j][1] = *(const uint32_t*)(p + 16);
                }
                #pragma unroll
                for (int i = 0; i < 4; i++)
                    #pragma unroll
                    for (int j = 0; j < 8; j++)
                        mma_h(c[i][j], a[i], b[j]);
            }
            __syncthreads();
            if (kt + 2 < KT) {
                issue(kt + 2); CP_COMMIT();
                CP_WAIT1(); __syncthreads();
            } else if (kt + 1 < KT) {
                CP_WAIT0(); __syncthreads();
            }
        }
        __syncthreads();   // protect smem before next tile's prologue

        // ---- epilogue (R11) ----
        int seg = 3, hh = 0;
        if (mode == 1) { int slot = (blockN + wn) >> 6; seg = slot >> 4; hh = slot & 15; }
        float wmax = -INFINITY;

        #pragma unroll
        for (int i = 0; i < 4; i++) {
            int gr = blockM + wm + i*16 + lr;
            float ds0 = 0.f, ds1 = 0.f;
            #pragma unroll
            for (int j = 0; j < 8; j++) {
                int gc = blockN + wn + j*8 + 2*lc;
                float b0 = bias[gc], b1 = bias[gc+1];
                float o0 = c[i][j][0] + b0, o1 = c[i][j][1] + b1;
                float o2 = c[i][j][2] + b0, o3 = c[i][j][3] + b1;
                if (relu) {
                    o0 = fmaxf(o0, 0.f); o1 = fmaxf(o1, 0.f);
                    o2 = fmaxf(o2, 0.f); o3 = fmaxf(o3, 0.f);
                }
                if (mode == 2)
                    wmax = fmaxf(wmax, fmaxf(fmaxf(o0, o1), fmaxf(o2, o3)));
                if (Cft) {
                    *(float2*)(Cft + (size_t)gr*N + gc)     = make_float2(o0, o1);
                    *(float2*)(Cft + (size_t)(gr+8)*N + gc) = make_float2(o2, o3);
                } else {
                    *(__half2*)(Cht + (size_t)gr*N + gc)     = __floats2half2_rn(o0, o1);
                    *(__half2*)(Cht + (size_t)(gr+8)*N + gc) = __floats2half2_rn(o2, o3);
                }
                if (mode == 1 && seg < 2) {
                    int d = gc & 63, bb = gr >> 12, nn = gr & 4095;
                    size_t hidx = ((size_t)((bb<<4) + hh)*4096 + nn)*64 + d;
                    __half* dst = (seg == 0) ? g_qh : g_kh;
                    *(__half2*)(dst + hidx)          = __floats2half2_rn(o0, o1);
                    *(__half2*)(dst + hidx + 8*64)   = __floats2half2_rn(o2, o3);
                    ds0 += o0*o0 + o1*o1;
                    ds1 += o2*o2 + o3*o3;
                }
            }
            if (mode == 1 && seg < 2) {
                ds0 += __shfl_xor_sync(0xffffffffu, ds0, 1);
                ds0 += __shfl_xor_sync(0xffffffffu, ds0, 2);
                ds1 += __shfl_xor_sync(0xffffffffu, ds1, 1);
                ds1 += __shfl_xor_sync(0xffffffffu, ds1, 2);
                if (lc == 0) {
                    int bb = gr >> 12, nn = gr & 4095;
                    size_t r0 = (size_t)((bb<<4) + hh)*4096 + nn;
                    float* dd = (seg == 0) ? g_qdiag : g_kdiag;
                    dd[r0]     = 0.0625f * ds0;
                    dd[r0 + 8] = 0.0625f * ds1;
                }
            }
        }
        if (mode == 2) {
            #pragma unroll
            for (int off = 16; off; off >>= 1)
                wmax = fmaxf(wmax, __shfl_xor_sync(0xffffffffu, wmax, off));
            if (lane == 0) atomicMaxF(&g_kstab[bz], wmax);
        }
    }
}

// ---------------- attnout GEMM: per head M=4096 N=64 K=256 ----------------
#define N64_HA  (256*HSTR*2)
#define N64_HB  (64*HSTR*2)
#define N64_ST  (N64_HA+N64_HB)
#define N64SMEM (2*N64_ST)

__global__ __launch_bounds__(256)
void hgemm_n64()
{
    extern __shared__ char smc[];
    const uint32_t sb = smem_u32(smc);
    const int tid  = threadIdx.x;
    const int lane = tid & 31;
    const int w    = tid >> 5;
    const int wm   = (w & 3) * 64;
    const int wn   = (w >> 2) * 32;
    const int lr   = lane >> 2;
    const int lc   = lane & 3;

    const int bh     = blockIdx.y;
    const int blockM = blockIdx.x * 256;
    const __half* A = g_qph  + (size_t)bh*Nn*Mf + (size_t)blockM*Mf;
    const __half* B = g_ctxTh + (size_t)bh*DHe*Mf;

    float c[4][4][4];
    #pragma unroll
    for (int i = 0; i < 4; i++)
        #pragma unroll
        for (int j = 0; j < 4; j++)
            #pragma unroll
            for (int t = 0; t < 4; t++) c[i][j][t] = 0.f;

    const int r8 = tid >> 3, cc8 = tid & 7;

    auto issue = [&](int kt) {
        const int buf = kt & 1;
        const uint32_t dA = sb + buf*N64_ST;
        const uint32_t dB = dA + N64_HA;
        const __half* As = A + kt*64;
        const __half* Bs = B + kt*64;
        #pragma unroll
        for (int it = 0; it < 8; it++) {
            int r = r8 + it*32;
            CP_ASYNC16(dA + r*(HSTR*2) + cc8*16, As + (size_t)r*Mf + cc8*8);
        }
        #pragma unroll
        for (int it = 0; it < 2; it++) {
            int r = r8 + it*32;
            CP_ASYNC16(dB + r*(HSTR*2) + cc8*16, Bs + (size_t)r*Mf + cc8*8);
        }
    };

    issue(0); CP_COMMIT();
    issue(1); CP_COMMIT();
    CP_WAIT1(); __syncthreads();

    const int KT = Mf/64;   // 4
    for (int kt = 0; kt < KT; kt++) {
        const char* bufA = smc + (kt & 1)*N64_ST;
        const char* bufB = bufA + N64_HA;

        #pragma unroll
        for (int ks = 0; ks < 4; ks++) {
            const int k0 = ks*16;
            uint32_t a[4][4], b[4][2];
            #pragma unroll
            for (int i = 0; i < 4; i++) {
                int r = wm + i*16 + lr;
                const char* p = bufA + (r*HSTR + k0 + lc*2)*2;
                a[i][0] = *(const uint32_t*)(p);
                a[i][1] = *(const uint32_t*)(p + 8*HSTR*2);
                a[i][2] = *(const uint32_t*)(p + 16);
                a[i][3] = *(const uint32_t*)(p + 8*HSTR*2 + 16);
            }
            #pragma unroll
            for (int j = 0; j < 4; j++) {
                int n = wn + j*8 + lr;
                const char* p = bufB + (n*HSTR + k0 + lc*2)*2;
                b[j][0] = *(const uint32_t*)(p);
                b[j][1] = *(const uint32_t*)(p + 16);
            }
            #pragma unroll
            for (int i = 0; i < 4; i++)
                #pragma unroll
                for (int j = 0; j < 4; j++)
                    mma_h(c[i][j], a[i], b[j]);
        }
        __syncthreads();
        if (kt + 2 < KT) {
            issue(kt + 2); CP_COMMIT();
            CP_WAIT1(); __syncthreads();
        } else if (kt + 1 < KT) {
            CP_WAIT0(); __syncthreads();
        }
    }

    const int bb = bh >> 4, h = bh & 15;
    #pragma unroll
    for (int i = 0; i < 4; i++) {
        int n0 = blockM + wm + i*16 + lr;
        float rd0 = 1.f / g_den[bh*Nn + n0];
        float rd1 = 1.f / g_den[bh*Nn + n0 + 8];
        size_t t0 = ((size_t)bb*Nn + n0)*Dm + h*64;
        size_t t1 = t0 + (size_t)8*Dm;
        #pragma unroll
        for (int j = 0; j < 4; j++) {
            int d = wn + j*8 + 2*lc;
            *(__half2*)(g_attnh + t0 + d) = __floats2half2_rn(c[i][j][0]*rd0, c[i][j][1]*rd0);
            *(__half2*)(g_attnh + t1 + d) = __floats2half2_rn(c[i][j][2]*rd1, c[i][j][3]*rd1);
        }
    }
}

// ---------------- init kstab ----------------
__global__ void init_kstab() {
    if (threadIdx.x < BH) g_kstab[threadIdx.x] = -INFINITY;
}

// ---------------- qexp ----------------
__global__ __launch_bounds__(256)
void qexp_kernel()
{
    const int row = blockIdx.x*8 + (threadIdx.x >> 5);
    const int lane = threadIdx.x & 31;
    const float4* xp4 = (const float4*)(g_qp + (size_t)row*Mf);
    float4 v0 = xp4[lane], v1 = xp4[lane+32];
    float mx = fmaxf(fmaxf(fmaxf(v0.x,v0.y),fmaxf(v0.z,v0.w)),
                     fmaxf(fmaxf(v1.x,v1.y),fmaxf(v1.z,v1.w)));
    #pragma unroll
    for (int off = 16; off; off >>= 1)
        mx = fmaxf(mx, __shfl_xor_sync(0xffffffffu, mx, off));
    float sh = g_qdiag[row] + mx;
    __half2* o = (__half2*)(g_qph + (size_t)row*Mf);
    o[2*lane]      = __floats2half2_rn(__expf(v0.x-sh)+EPSKF, __expf(v0.y-sh)+EPSKF);
    o[2*lane+1]    = __floats2half2_rn(__expf(v0.z-sh)+EPSKF, __expf(v0.w-sh)+EPSKF);
    o[2*lane+64]   = __floats2half2_rn(__expf(v1.x-sh)+EPSKF, __expf(v1.y-sh)+EPSKF);
    o[2*lane+65]   = __floats2half2_rn(__expf(v1.z-sh)+EPSKF, __expf(v1.w-sh)+EPSKF);
}

// ---------------- fused kexp + ksum partials ----------------
__global__ __launch_bounds__(256)
void kexp_ksum_kernel()
{
    const int bh = blockIdx.x;
    const int part = blockIdx.y;
    const int m = threadIdx.x;
    const float stab = g_kstab[bh];
    const int row0 = bh*Nn + part*256;
    float* kp = g_kp + (size_t)bh * Nn * Mf + (size_t)part * 256 * Mf + m;
    float acc = 0.f;
    #pragma unroll 4
    for (int n = 0; n < 256; n++) {
        float xp = kp[(size_t)n * Mf];
        float kv = RATIOF * (__expf(xp - g_kdiag[row0 + n] - stab) + EPSKF);
        kp[(size_t)n * Mf] = kv;
        acc += kv;
    }
    g_ksum_part[(part*BH + bh)*Mf + m] = acc;
}
__global__ __launch_bounds__(256)
void ksum_reduce_kernel()
{
    const int bh = blockIdx.x;
    const int m = threadIdx.x;
    float acc = 0.f;
    #pragma unroll
    for (int p = 0; p < 16; p++) acc += g_ksum_part[(p*BH + bh)*Mf + m];
    g_ksum[bh*Mf + m] = acc;
}

// ---------------- den ----------------
__global__ __launch_bounds__(256)
void den_kernel()
{
    const int row = blockIdx.x*8 + (threadIdx.x >> 5);
    const int lane = threadIdx.x & 31;
    const int bh = row >> 12;
    uint4 qv = ((const uint4*)(g_qph + (size_t)row*Mf))[lane];
    const float4* ks4 = (const float4*)(g_ksum + bh*Mf);
    float4 k0 = ks4[2*lane], k1 = ks4[2*lane+1];
    float2 q0 = __half22float2(*(__half2*)&qv.x);
    float2 q1 = __half22float2(*(((__half2*)&qv.x)+1));
    float2 q2 = __half22float2(*(__half2*)&qv.z);
    float2 q3 = __half22float2(*(((__half2*)&qv.z)+1));
    float s = q0.x*k0.x + q0.y*k0.y + q1.x*k0.z + q1.y*k0.w
            + q2.x*k1.x + q2.y*k1.y + q3.x*k1.z + q3.y*k1.w;
    #pragma unroll
    for (int off = 16; off; off >>= 1) s += __shfl_xor_sync(0xffffffffu, s, off);
    if (lane == 0) g_den[row] = s;
}

// ---------------- ctx (packed f32x2 FFMA2), writes ctx^T half directly ----
__global__ __launch_bounds__(256)
void ctx_kernel()
{
    __shared__ float kpc[32][64];
    __shared__ float vc [32][64];

    const int bh = blockIdx.x;
    const int mtile = blockIdx.y;
    const int b = bh >> 4, h = bh & 15;
    const int tid = threadIdx.x;
    const int tx = tid & 15;
    const int ty = tid >> 4;

    uint64_t acc2[4][2];
    const uint64_t z2 = pack2(0.f);
    #pragma unroll
    for (int i = 0; i < 4; i++) { acc2[i][0] = z2; acc2[i][1] = z2; }

    const float* kpBase = g_kp + (size_t)bh * Nn * Mf + mtile*64;
    const float* vBase  = g_qkv + (size_t)b * Nn * QKVS + 2*Dm + h*DHe;

    for (int n0 = 0; n0 < Nn; n0 += 32) {
        #pragma unroll
        for (int it = 0; it < 8; it++) {
            int j = it*256 + tid;
            int nn = j >> 6, cq = j & 63;
            kpc[nn][cq] = kpBase[(size_t)(n0+nn)*Mf + cq];
            vc [nn][cq] = vBase [(size_t)(n0+nn)*QKVS + cq];
        }
        __syncthreads();
        #pragma unroll
        for (int nn = 0; nn < 32; nn++) {
            float4 kf = *(const float4*)&kpc[nn][ty*4];
            float4 vf = *(const float4*)&vc [nn][tx*4];
            uint64_t v01, v23;
            asm("mov.b64 %0, {%1, %2};" : "=l"(v01) : "f"(vf.x), "f"(vf.y));
            asm("mov.b64 %0, {%1, %2};" : "=l"(v23) : "f"(vf.z), "f"(vf.w));
            float kr[4] = {kf.x,kf.y,kf.z,kf.w};
            #pragma unroll
            for (int i = 0; i < 4; i++) {
                uint64_t kk = pack2(kr[i]);
                ffma2(acc2[i][0], kk, v01);
                ffma2(acc2[i][1], kk, v23);
            }
        }
        __syncthreads();
    }
    // write transposed half directly: ctxTh[bh][d][m]
    __half* dst = g_ctxTh + (size_t)bh*DHe*Mf;
    #pragma unroll
    for (int i = 0; i < 4; i++) {
        int m = mtile*64 + ty*4 + i;
        float2 lo = unpack2(acc2[i][0]);
        float2 hi = unpack2(acc2[i][1]);
        dst[(tx*4+0)*Mf + m] = __float2half_rn(lo.x);
        dst[(tx*4+1)*Mf + m] = __float2half_rn(lo.y);
        dst[(tx*4+2)*Mf + m] = __float2half_rn(hi.x);
        dst[(tx*4+3)*Mf + m] = __float2half_rn(hi.y);
    }
}

// ---------------- LayerNorm(a + b) * g + be ----------------
__global__ __launch_bounds__(256)
void ln_kernel(const float* __restrict__ A, const float* __restrict__ Bc,
               const float* __restrict__ g, const float* __restrict__ be,
               float* __restrict__ outf, __half* __restrict__ outh)
{
    __shared__ float s1s[8], s2s[8], bc[2];
    const int row = blockIdx.x;
    const int tid = threadIdx.x;
    const int lane = tid & 31, wid = tid >> 5;

    const float4* a4 = (const float4*)(A  + (size_t)row*Dm);
    const float4* b4 = (const float4*)(Bc + (size_t)row*Dm);
    float4 va = a4[tid], vb = b4[tid];
    float4 v = make_float4(va.x+vb.x, va.y+vb.y, va.z+vb.z, va.w+vb.w);

    float s1 = v.x+v.y+v.z+v.w;
    float s2 = v.x*v.x+v.y*v.y+v.z*v.z+v.w*v.w;
    #pragma unroll
    for (int off = 16; off; off >>= 1) {
        s1 += __shfl_xor_sync(0xffffffffu, s1, off);
        s2 += __shfl_xor_sync(0xffffffffu, s2, off);
    }
    if (lane == 0) { s1s[wid] = s1; s2s[wid] = s2; }
    __syncthreads();
    if (tid == 0) {
        float S1 = 0.f, S2 = 0.f;
        #pragma unroll
        for (int i = 0; i < 8; i++) { S1 += s1s[i]; S2 += s2s[i]; }
        float mu = S1 * (1.f/Dm);
        float var = S2 * (1.f/Dm) - mu*mu;
        bc[0] = mu;
        bc[1] = rsqrtf(var + LNEPS);
    }
    __syncthreads();
    float mu = bc[0], rstd = bc[1];

    float4 gg = ((const float4*)g)[tid];
    float4 bb = ((const float4*)be)[tid];
    float4 o = make_float4((v.x-mu)*rstd*gg.x + bb.x,
                           (v.y-mu)*rstd*gg.y + bb.y,
                           (v.z-mu)*rstd*gg.z + bb.z,
                           (v.w-mu)*rstd*gg.w + bb.w);
    ((float4*)(outf + (size_t)row*Dm))[tid] = o;
    if (outh) {
        __half2* oh = (__half2*)(outh + (size_t)row*Dm) + 2*tid;
        oh[0] = __floats2half2_rn(o.x, o.y);
        oh[1] = __floats2half2_rn(o.z, o.w);
    }
}

// ---------------- host ----------------
static inline void launch_hgemm(const __half* A, const __half* W, const float* bias,
                                float* Cf, __half* Ch, int M, int N, int K, int relu,
                                int mode, size_t zsA, size_t zsC, int gz)
{
    int gx = N / 128, gy = M / 256;
    int tiles = gx * gy * gz;
    int grid = tiles < GEMM_GRID ? tiles : GEMM_GRID;
    hgemm<<<grid, 256, HSMEM>>>(A, W, bias, Cf, Ch, M, N, K, relu, mode, zsA, zsC,
                                tiles, gx, gy);
}

extern "C" void kernel_launch(void* const* d_in, const int* in_sizes, int n_in,
                              void* d_out, int out_size)
{
    const float* video = (const float*)d_in[0];
    const float* Wq    = (const float*)d_in[1];
    const float* bq    = (const float*)d_in[2];
    const float* Wk    = (const float*)d_in[3];
    const float* bk    = (const float*)d_in[4];
    const float* Wv    = (const float*)d_in[5];
    const float* bv    = (const float*)d_in[6];
    const float* Wo    = (const float*)d_in[7];
    const float* bo    = (const float*)d_in[8];
    const float* proj  = (const float*)d_in[9];
    const float* W1    = (const float*)d_in[10];
    const float* b1    = (const float*)d_in[11];
    const float* W2    = (const float*)d_in[12];
    const float* b2    = (const float*)d_in[13];
    const float* g2    = (const float*)d_in[14];
    const float* be2   = (const float*)d_in[15];
    const float* g3    = (const float*)d_in[16];
    const float* be3   = (const float*)d_in[17];
    float* out = (float*)d_out;

    __half *vidh, *wqkvh, *woh, *w1h, *w2h, *attnh, *x1h, *ffh, *qh, *kh, *projh;
    float *bqkv, *qkv, *y, *x1, *qp, *kp, *zerob;
    cudaGetSymbolAddress((void**)&vidh,  g_vidh);
    cudaGetSymbolAddress((void**)&wqkvh, g_wqkvh);
    cudaGetSymbolAddress((void**)&bqkv,  g_bqkv);
    cudaGetSymbolAddress((void**)&woh,   g_woh);
    cudaGetSymbolAddress((void**)&w1h,   g_w1h);
    cudaGetSymbolAddress((void**)&w2h,   g_w2h);
    cudaGetSymbolAddress((void**)&qkv,   g_qkv);
    cudaGetSymbolAddress((void**)&attnh, g_attnh);
    cudaGetSymbolAddress((void**)&x1h,   g_x1h);
    cudaGetSymbolAddress((void**)&ffh,   g_ffh);
    cudaGetSymbolAddress((void**)&y,     g_y);
    cudaGetSymbolAddress((void**)&x1,    g_x1);
    cudaGetSymbolAddress((void**)&qh,    g_qh);
    cudaGetSymbolAddress((void**)&kh,    g_kh);
    cudaGetSymbolAddress((void**)&projh, g_projh);
    cudaGetSymbolAddress((void**)&qp,    g_qp);
    cudaGetSymbolAddress((void**)&kp,    g_kp);
    cudaGetSymbolAddress((void**)&zerob, g_zerob);

    cudaFuncSetAttribute(hgemm,     cudaFuncAttributeMaxDynamicSharedMemorySize, HSMEM);
    cudaFuncSetAttribute(hgemm_n64, cudaFuncAttributeMaxDynamicSharedMemorySize, N64SMEM);

    // 0. conversions (R11 layout: separate launches)
    pack_qkvh<<<(3*Dm*Dm + 255)/256, 256>>>(Wq, Wk, Wv, bq, bk, bv);
    pack_projh<<<(Mf*DHe + 255)/256, 256>>>(proj);
    f2h_kernel<<<(Tt*Dm/4 + 255)/256, 256>>>(video, vidh, Tt*Dm/4);
    f2h_kernel<<<(Dm*Dm/4 + 255)/256, 256>>>(Wo, woh, Dm*Dm/4);
    f2h_kernel<<<(DFFe*Dm/4 + 255)/256, 256>>>(W1, w1h, DFFe*Dm/4);
    f2h_kernel<<<(Dm*DFFe/4 + 255)/256, 256>>>(W2, w2h, Dm*DFFe/4);
    init_kstab<<<1, 64>>>();

    // 1. fused QKV projection (mode 1: fp32 qkv + qh/kh half + diag)
    launch_hgemm(vidh, wqkvh, bqkv, qkv, nullptr, Tt, QKVS, Dm, 0, 1, 0, 0, 1);

    // 2. feature-map GEMMs (batched per head); feat-k fuses kstab max (mode 2)
    launch_hgemm(qh, projh, zerob, qp, nullptr, Nn, Mf, DHe, 0, 0,
                 (size_t)Nn*DHe, (size_t)Nn*Mf, BH);
    launch_hgemm(kh, projh, zerob, kp, nullptr, Nn, Mf, DHe, 0, 2,
                 (size_t)Nn*DHe, (size_t)Nn*Mf, BH);

    // 3. exps (k exp fused with ksum partials)
    qexp_kernel<<<(BH*Nn)/8, 256>>>();
    kexp_ksum_kernel<<<dim3(BH, 16), 256>>>();
    ksum_reduce_kernel<<<BH, 256>>>();

    // 4. linear attention
    den_kernel<<<(BH*Nn)/8, 256>>>();
    ctx_kernel<<<dim3(BH, Mf/64), 256>>>();        // writes ctxTh directly
    hgemm_n64<<<dim3(Nn/256, BH), 256, N64SMEM>>>();

    // 5. output projection + residual LN
    launch_hgemm(attnh, woh, bo, y, nullptr, Tt, Dm, Dm, 0, 0, 0, 0, 1);
    ln_kernel<<<Tt, 256>>>(video, y, g2, be2, x1, x1h);

    // 6. FFN
    launch_hgemm(x1h, w1h, b1, nullptr, ffh, Tt, DFFe, Dm, 1, 0, 0, 0, 1);
    launch_hgemm(ffh, w2h, b2, y, nullptr, Tt, Dm, DFFe, 0, 0, 0, 0, 1);
    ln_kernel<<<Tt, 256>>>(x1, y, g3, be3, out, nullptr);
}

// round 15
// speedup vs baseline: 1.4802x; 1.0061x over previous
#include <cuda_runtime.h>
#include <cuda_fp16.h>
#include <math.h>
#include <stdint.h>

// ---------------- problem constants ----------------
#define Bb     4
#define Nn     4096
#define Dm     1024
#define Hh     16
#define DHe    64
#define DFFe   4096
#define Mf     256
#define BH     (Bb*Hh)          // 64
#define Tt     (Bb*Nn)          // 16384
#define QKVS   3072
#define NORMF  0.3535533905932738f   // 64^-0.25
#define RATIOF 0.0625f               // 256^-0.5
#define EPSKF  1e-4f
#define LNEPS  1e-5f
#define GEMM_GRID 296

// ---------------- scratch (device globals, no allocs) ----------------
__device__ __align__(256) __half g_vidh [Tt*Dm];
__device__ __align__(256) __half g_wqkvh[3*Dm*Dm];
__device__ float  g_bqkv[3*Dm];
__device__ __align__(256) __half g_woh  [Dm*Dm];
__device__ __align__(256) __half g_w1h  [DFFe*Dm];
__device__ __align__(256) __half g_w2h  [Dm*DFFe];
__device__ float  g_qkv [Tt*QKVS];    // fused q|k|v fp32 (only v slice written/read)
__device__ __align__(256) __half g_qh  [BH*Nn*DHe];
__device__ __align__(256) __half g_kh  [BH*Nn*DHe];
__device__ __align__(256) __half g_projh[Mf*DHe];
__device__ __align__(256) __half g_attnh[Tt*Dm];
__device__ __align__(256) __half g_x1h [Tt*Dm];
__device__ __align__(256) __half g_ffh [Tt*DFFe];
__device__ float  g_qp  [BH*Nn*Mf];
__device__ float  g_kp  [BH*Nn*Mf];
__device__ __align__(256) __half g_qph [BH*Nn*Mf];
__device__ float  g_qdiag[BH*Nn];
__device__ float  g_kdiag[BH*Nn];
__device__ float  g_kstab[BH];
__device__ float  g_ksum[BH*Mf];
__device__ float  g_ksum_part[16*BH*Mf];
__device__ float  g_den [BH*Nn];
__device__ __align__(256) __half g_ctxTh[BH*DHe*Mf];  // ctx^T half [bh][d][m]
__device__ float  g_y   [Tt*Dm];
__device__ float  g_x1  [Tt*Dm];
__device__ float  g_zerob[Mf];

// ---------------- PTX helpers ----------------
__device__ __forceinline__ uint32_t smem_u32(const void* p){
    uint32_t a;
    asm("{ .reg .u64 t; cvta.to.shared.u64 t, %1; cvt.u32.u64 %0, t; }" : "=r"(a) : "l"(p));
    return a;
}
#define CP_ASYNC16(dst, src) \
    asm volatile("cp.async.cg.shared.global [%0], [%1], 16;" :: "r"(dst), "l"(src))
#define CP_COMMIT() asm volatile("cp.async.commit_group;" ::: "memory")
#define CP_WAIT1()  asm volatile("cp.async.wait_group 1;" ::: "memory")
#define CP_WAIT0()  asm volatile("cp.async.wait_group 0;" ::: "memory")

__device__ __forceinline__ void mma_h(float c[4], const uint32_t a[4], const uint32_t b[2]){
    asm volatile("mma.sync.aligned.m16n8k16.row.col.f32.f16.f16.f32 "
        "{%0,%1,%2,%3}, {%4,%5,%6,%7}, {%8,%9}, {%0,%1,%2,%3};"
        : "+f"(c[0]), "+f"(c[1]), "+f"(c[2]), "+f"(c[3])
        : "r"(a[0]), "r"(a[1]), "r"(a[2]), "r"(a[3]), "r"(b[0]), "r"(b[1]));
}
__device__ __forceinline__ void atomicMaxF(float* addr, float v) {
    int old = __float_as_int(*addr);
    while (__int_as_float(old) < v) {
        int assumed = old;
        old = atomicCAS((int*)addr, assumed, __float_as_int(v));
        if (old == assumed) break;
    }
}
__device__ __forceinline__ uint64_t pack2(float x){
    uint64_t r; asm("mov.b64 %0, {%1, %1};" : "=l"(r) : "f"(x)); return r;
}
__device__ __forceinline__ void ffma2(uint64_t& c, uint64_t a, uint64_t b){
    asm("fma.rn.f32x2 %0, %1, %2, %0;" : "+l"(c) : "l"(a), "l"(b));
}
__device__ __forceinline__ float2 unpack2(uint64_t v){
    float lo, hi; asm("mov.b64 {%0, %1}, %2;" : "=f"(lo), "=f"(hi) : "l"(v));
    return make_float2(lo, hi);
}

// ---------------- conversion kernels ----------------
__global__ __launch_bounds__(256)
void f2h_kernel(const float* __restrict__ src, __half* __restrict__ dst, int n4)
{
    int i = blockIdx.x*256 + threadIdx.x;
    if (i < n4) {
        float4 v = ((const float4*)src)[i];
        __half2* d = (__half2*)dst + 2*i;
        d[0] = __floats2half2_rn(v.x, v.y);
        d[1] = __floats2half2_rn(v.z, v.w);
    }
}
__global__ __launch_bounds__(256)
void pack_qkvh(const float* __restrict__ Wq, const float* __restrict__ Wk,
               const float* __restrict__ Wv, const float* __restrict__ bq,
               const float* __restrict__ bk, const float* __restrict__ bv)
{
    size_t i = (size_t)blockIdx.x*256 + threadIdx.x;
    if (i < (size_t)3*Dm*Dm) {
        int seg = (int)(i >> 20);
        size_t off = i & 0xFFFFF;
        const float* s = (seg == 0) ? Wq : (seg == 1) ? Wk : Wv;
        g_wqkvh[i] = __float2half_rn(s[off]);
    }
    if (i < 3*Dm)
        g_bqkv[i] = (i < Dm) ? bq[i] : (i < 2*Dm) ? bk[i-Dm] : bv[i-2*Dm];
}
__global__ __launch_bounds__(256)
void pack_projh(const float* __restrict__ proj)
{
    int i = blockIdx.x*256 + threadIdx.x;
    if (i < Mf*DHe) g_projh[i] = __float2half_rn(proj[i] * NORMF);
}

// ---------------- fp16 mma GEMM-NT, persistent tiles (R14 base) ------------
#define HSTR    72
#define HA_BY   (256*HSTR*2)
#define HB_BY   (128*HSTR*2)
#define HSTAGE  (HA_BY+HB_BY)
#define HSMEM   (2*HSTAGE)       // 110592

__global__ __launch_bounds__(256)
void hgemm(const __half* __restrict__ A, const __half* __restrict__ W,
           const float* __restrict__ bias, float* __restrict__ Cf,
           __half* __restrict__ Ch, int M, int N, int K, int relu,
           int mode, size_t zsA, size_t zsC, int tiles, int gx, int gy)
{
    extern __shared__ char smc[];
    const uint32_t sb = smem_u32(smc);
    const int tid  = threadIdx.x;
    const int lane = tid & 31;
    const int w    = tid >> 5;
    const int wm   = (w & 3) * 64;
    const int wn   = (w >> 2) * 64;
    const int lr   = lane >> 2;
    const int lc   = lane & 3;
    const int r8 = tid >> 3, cc8 = tid & 7;
    const int KT = K / 64;

    for (int t = blockIdx.x; t < tiles; t += gridDim.x) {
        const int bx = t % gx;
        const int rr = t / gx;
        const int by = rr % gy;
        const int bz = rr / gy;

        const __half* At = A + (size_t)bz * zsA;
        float* Cft = Cf ? Cf + (size_t)bz * zsC : (float*)0;
        __half* Cht = Ch ? Ch + (size_t)bz * zsC : (__half*)0;

        const int blockM = by * 256;
        const int blockN = bx * 128;

        float c[4][8][4];
        #pragma unroll
        for (int i = 0; i < 4; i++)
            #pragma unroll
            for (int j = 0; j < 8; j++)
                #pragma unroll
                for (int tt = 0; tt < 4; tt++) c[i][j][tt] = 0.f;

        const __half* Abase = At + (size_t)blockM * K;
        const __half* Wbase = W + (size_t)blockN * K;

        auto issue = [&](int kt) {
            const int buf = kt & 1;
            const uint32_t dA = sb + buf*HSTAGE;
            const uint32_t dB = dA + HA_BY;
            const __half* As = Abase + kt*64;
            const __half* Ws = Wbase + kt*64;
            #pragma unroll
            for (int it = 0; it < 8; it++) {
                int r = r8 + it*32;
                CP_ASYNC16(dA + r*(HSTR*2) + cc8*16, As + (size_t)r*K + cc8*8);
            }
            #pragma unroll
            for (int it = 0; it < 4; it++) {
                int r = r8 + it*32;
                CP_ASYNC16(dB + r*(HSTR*2) + cc8*16, Ws + (size_t)r*K + cc8*8);
            }
        };

        issue(0); CP_COMMIT();
        if (KT > 1) { issue(1); CP_COMMIT(); CP_WAIT1(); }
        else        { CP_WAIT0(); }
        __syncthreads();

        for (int kt = 0; kt < KT; kt++) {
            const char* bufA = smc + (kt & 1)*HSTAGE;
            const char* bufB = bufA + HA_BY;

            #pragma unroll
            for (int ks = 0; ks < 4; ks++) {
                const int k0 = ks*16;
                uint32_t a[4][4], b[8][2];
                #pragma unroll
                for (int i = 0; i < 4; i++) {
                    int r = wm + i*16 + lr;
                    const char* p = bufA + (r*HSTR + k0 + lc*2)*2;
                    a[i][0] = *(const uint32_t*)(p);
                    a[i][1] = *(const uint32_t*)(p + 8*HSTR*2);
                    a[i][2] = *(const uint32_t*)(p + 16);
                    a[i][3] = *(const uint32_t*)(p + 8*HSTR*2 + 16);
                }
                #pragma unroll
                for (int j = 0; j < 8; j++) {
                    int n = wn + j*8 + lr;
                    const char* p = bufB + (n*HSTR + k0 + lc*2)*2;
                    b[j][0] = *(const uint32_t*)(p);
                    b[j][1] = *(const uint32_t*)(p + 16);
                }
                #pragma unroll
                for (int i = 0; i < 4; i++)
                    #pragma unroll
                    for (int j = 0; j < 8; j++)
                        mma_h(c[i][j], a[i], b[j]);
            }
            __syncthreads();
            if (kt + 2 < KT) {
                issue(kt + 2); CP_COMMIT();
                CP_WAIT1(); __syncthreads();
            } else if (kt + 1 < KT) {
                CP_WAIT0(); __syncthreads();
            }
        }
        __syncthreads();   // protect smem before next tile's prologue

        // ---- epilogue (R14 + dead q/k fp32 stores skipped) ----
        int seg = 3, hh = 0;
        if (mode == 1) { int slot = (blockN + wn) >> 6; seg = slot >> 4; hh = slot & 15; }
        const bool storeF = (Cft != 0) && (mode != 1 || seg == 2);
        float wmax = -INFINITY;

        #pragma unroll
        for (int i = 0; i < 4; i++) {
            int gr = blockM + wm + i*16 + lr;
            float ds0 = 0.f, ds1 = 0.f;
            #pragma unroll
            for (int j = 0; j < 8; j++) {
                int gc = blockN + wn + j*8 + 2*lc;
                float b0 = bias[gc], b1 = bias[gc+1];
                float o0 = c[i][j][0] + b0, o1 = c[i][j][1] + b1;
                float o2 = c[i][j][2] + b0, o3 = c[i][j][3] + b1;
                if (relu) {
                    o0 = fmaxf(o0, 0.f); o1 = fmaxf(o1, 0.f);
                    o2 = fmaxf(o2, 0.f); o3 = fmaxf(o3, 0.f);
                }
                if (mode == 2)
                    wmax = fmaxf(wmax, fmaxf(fmaxf(o0, o1), fmaxf(o2, o3)));
                if (storeF) {
                    *(float2*)(Cft + (size_t)gr*N + gc)     = make_float2(o0, o1);
                    *(float2*)(Cft + (size_t)(gr+8)*N + gc) = make_float2(o2, o3);
                } else if (Cht) {
                    *(__half2*)(Cht + (size_t)gr*N + gc)     = __floats2half2_rn(o0, o1);
                    *(__half2*)(Cht + (size_t)(gr+8)*N + gc) = __floats2half2_rn(o2, o3);
                }
                if (mode == 1 && seg < 2) {
                    int d = gc & 63, bb = gr >> 12, nn = gr & 4095;
                    size_t hidx = ((size_t)((bb<<4) + hh)*4096 + nn)*64 + d;
                    __half* dst = (seg == 0) ? g_qh : g_kh;
                    *(__half2*)(dst + hidx)          = __floats2half2_rn(o0, o1);
                    *(__half2*)(dst + hidx + 8*64)   = __floats2half2_rn(o2, o3);
                    ds0 += o0*o0 + o1*o1;
                    ds1 += o2*o2 + o3*o3;
                }
            }
            if (mode == 1 && seg < 2) {
                ds0 += __shfl_xor_sync(0xffffffffu, ds0, 1);
                ds0 += __shfl_xor_sync(0xffffffffu, ds0, 2);
                ds1 += __shfl_xor_sync(0xffffffffu, ds1, 1);
                ds1 += __shfl_xor_sync(0xffffffffu, ds1, 2);
                if (lc == 0) {
                    int bb = gr >> 12, nn = gr & 4095;
                    size_t r0 = (size_t)((bb<<4) + hh)*4096 + nn;
                    float* dd = (seg == 0) ? g_qdiag : g_kdiag;
                    dd[r0]     = 0.0625f * ds0;
                    dd[r0 + 8] = 0.0625f * ds1;
                }
            }
        }
        if (mode == 2) {
            #pragma unroll
            for (int off = 16; off; off >>= 1)
                wmax = fmaxf(wmax, __shfl_xor_sync(0xffffffffu, wmax, off));
            if (lane == 0) atomicMaxF(&g_kstab[bz], wmax);
        }
    }
}

// ---------------- attnout GEMM: per head M=4096 N=64 K=256 ----------------
#define N64_HA  (256*HSTR*2)
#define N64_HB  (64*HSTR*2)
#define N64_ST  (N64_HA+N64_HB)
#define N64SMEM (2*N64_ST)

__global__ __launch_bounds__(256)
void hgemm_n64()
{
    extern __shared__ char smc[];
    const uint32_t sb = smem_u32(smc);
    const int tid  = threadIdx.x;
    const int lane = tid & 31;
    const int w    = tid >> 5;
    const int wm   = (w & 3) * 64;
    const int wn   = (w >> 2) * 32;
    const int lr   = lane >> 2;
    const int lc   = lane & 3;

    const int bh     = blockIdx.y;
    const int blockM = blockIdx.x * 256;
    const __half* A = g_qph  + (size_t)bh*Nn*Mf + (size_t)blockM*Mf;
    const __half* B = g_ctxTh + (size_t)bh*DHe*Mf;

    float c[4][4][4];
    #pragma unroll
    for (int i = 0; i < 4; i++)
        #pragma unroll
        for (int j = 0; j < 4; j++)
            #pragma unroll
            for (int t = 0; t < 4; t++) c[i][j][t] = 0.f;

    const int r8 = tid >> 3, cc8 = tid & 7;

    auto issue = [&](int kt) {
        const int buf = kt & 1;
        const uint32_t dA = sb + buf*N64_ST;
        const uint32_t dB = dA + N64_HA;
        const __half* As = A + kt*64;
        const __half* Bs = B + kt*64;
        #pragma unroll
        for (int it = 0; it < 8; it++) {
            int r = r8 + it*32;
            CP_ASYNC16(dA + r*(HSTR*2) + cc8*16, As + (size_t)r*Mf + cc8*8);
        }
        #pragma unroll
        for (int it = 0; it < 2; it++) {
            int r = r8 + it*32;
            CP_ASYNC16(dB + r*(HSTR*2) + cc8*16, Bs + (size_t)r*Mf + cc8*8);
        }
    };

    issue(0); CP_COMMIT();
    issue(1); CP_COMMIT();
    CP_WAIT1(); __syncthreads();

    const int KT = Mf/64;   // 4
    for (int kt = 0; kt < KT; kt++) {
        const char* bufA = smc + (kt & 1)*N64_ST;
        const char* bufB = bufA + N64_HA;

        #pragma unroll
        for (int ks = 0; ks < 4; ks++) {
            const int k0 = ks*16;
            uint32_t a[4][4], b[4][2];
            #pragma unroll
            for (int i = 0; i < 4; i++) {
                int r = wm + i*16 + lr;
                const char* p = bufA + (r*HSTR + k0 + lc*2)*2;
                a[i][0] = *(const uint32_t*)(p);
                a[i][1] = *(const uint32_t*)(p + 8*HSTR*2);
                a[i][2] = *(const uint32_t*)(p + 16);
                a[i][3] = *(const uint32_t*)(p + 8*HSTR*2 + 16);
            }
            #pragma unroll
            for (int j = 0; j < 4; j++) {
                int n = wn + j*8 + lr;
                const char* p = bufB + (n*HSTR + k0 + lc*2)*2;
                b[j][0] = *(const uint32_t*)(p);
                b[j][1] = *(const uint32_t*)(p + 16);
            }
            #pragma unroll
            for (int i = 0; i < 4; i++)
                #pragma unroll
                for (int j = 0; j < 4; j++)
                    mma_h(c[i][j], a[i], b[j]);
        }
        __syncthreads();
        if (kt + 2 < KT) {
            issue(kt + 2); CP_COMMIT();
            CP_WAIT1(); __syncthreads();
        } else if (kt + 1 < KT) {
            CP_WAIT0(); __syncthreads();
        }
    }

    const int bb = bh >> 4, h = bh & 15;
    #pragma unroll
    for (int i = 0; i < 4; i++) {
        int n0 = blockM + wm + i*16 + lr;
        float rd0 = 1.f / g_den[bh*Nn + n0];
        float rd1 = 1.f / g_den[bh*Nn + n0 + 8];
        size_t t0 = ((size_t)bb*Nn + n0)*Dm + h*64;
        size_t t1 = t0 + (size_t)8*Dm;
        #pragma unroll
        for (int j = 0; j < 4; j++) {
            int d = wn + j*8 + 2*lc;
            *(__half2*)(g_attnh + t0 + d) = __floats2half2_rn(c[i][j][0]*rd0, c[i][j][1]*rd0);
            *(__half2*)(g_attnh + t1 + d) = __floats2half2_rn(c[i][j][2]*rd1, c[i][j][3]*rd1);
        }
    }
}

// ---------------- init kstab ----------------
__global__ void init_kstab() {
    if (threadIdx.x < BH) g_kstab[threadIdx.x] = -INFINITY;
}

// ---------------- qexp ----------------
__global__ __launch_bounds__(256)
void qexp_kernel()
{
    const int row = blockIdx.x*8 + (threadIdx.x >> 5);
    const int lane = threadIdx.x & 31;
    const float4* xp4 = (const float4*)(g_qp + (size_t)row*Mf);
    float4 v0 = xp4[lane], v1 = xp4[lane+32];
    float mx = fmaxf(fmaxf(fmaxf(v0.x,v0.y),fmaxf(v0.z,v0.w)),
                     fmaxf(fmaxf(v1.x,v1.y),fmaxf(v1.z,v1.w)));
    #pragma unroll
    for (int off = 16; off; off >>= 1)
        mx = fmaxf(mx, __shfl_xor_sync(0xffffffffu, mx, off));
    float sh = g_qdiag[row] + mx;
    __half2* o = (__half2*)(g_qph + (size_t)row*Mf);
    o[2*lane]      = __floats2half2_rn(__expf(v0.x-sh)+EPSKF, __expf(v0.y-sh)+EPSKF);
    o[2*lane+1]    = __floats2half2_rn(__expf(v0.z-sh)+EPSKF, __expf(v0.w-sh)+EPSKF);
    o[2*lane+64]   = __floats2half2_rn(__expf(v1.x-sh)+EPSKF, __expf(v1.y-sh)+EPSKF);
    o[2*lane+65]   = __floats2half2_rn(__expf(v1.z-sh)+EPSKF, __expf(v1.w-sh)+EPSKF);
}

// ---------------- fused kexp + ksum partials ----------------
__global__ __launch_bounds__(256)
void kexp_ksum_kernel()
{
    const int bh = blockIdx.x;
    const int part = blockIdx.y;
    const int m = threadIdx.x;
    const float stab = g_kstab[bh];
    const int row0 = bh*Nn + part*256;
    float* kp = g_kp + (size_t)bh * Nn * Mf + (size_t)part * 256 * Mf + m;
    float acc = 0.f;
    #pragma unroll 4
    for (int n = 0; n < 256; n++) {
        float xp = kp[(size_t)n * Mf];
        float kv = RATIOF * (__expf(xp - g_kdiag[row0 + n] - stab) + EPSKF);
        kp[(size_t)n * Mf] = kv;
        acc += kv;
    }
    g_ksum_part[(part*BH + bh)*Mf + m] = acc;
}
__global__ __launch_bounds__(256)
void ksum_reduce_kernel()
{
    const int bh = blockIdx.x;
    const int m = threadIdx.x;
    float acc = 0.f;
    #pragma unroll
    for (int p = 0; p < 16; p++) acc += g_ksum_part[(p*BH + bh)*Mf + m];
    g_ksum[bh*Mf + m] = acc;
}

// ---------------- den ----------------
__global__ __launch_bounds__(256)
void den_kernel()
{
    const int row = blockIdx.x*8 + (threadIdx.x >> 5);
    const int lane = threadIdx.x & 31;
    const int bh = row >> 12;
    uint4 qv = ((const uint4*)(g_qph + (size_t)row*Mf))[lane];
    const float4* ks4 = (const float4*)(g_ksum + bh*Mf);
    float4 k0 = ks4[2*lane], k1 = ks4[2*lane+1];
    float2 q0 = __half22float2(*(__half2*)&qv.x);
    float2 q1 = __half22float2(*(((__half2*)&qv.x)+1));
    float2 q2 = __half22float2(*(__half2*)&qv.z);
    float2 q3 = __half22float2(*(((__half2*)&qv.z)+1));
    float s = q0.x*k0.x + q0.y*k0.y + q1.x*k0.z + q1.y*k0.w
            + q2.x*k1.x + q2.y*k1.y + q3.x*k1.z + q3.y*k1.w;
    #pragma unroll
    for (int off = 16; off; off >>= 1) s += __shfl_xor_sync(0xffffffffu, s, off);
    if (lane == 0) g_den[row] = s;
}

// ---------------- ctx (packed f32x2 FFMA2), writes ctx^T half directly ----
__global__ __launch_bounds__(256)
void ctx_kernel()
{
    __shared__ float kpc[32][64];
    __shared__ float vc [32][64];

    const int bh = blockIdx.x;
    const int mtile = blockIdx.y;
    const int b = bh >> 4, h = bh & 15;
    const int tid = threadIdx.x;
    const int tx = tid & 15;
    const int ty = tid >> 4;

    uint64_t acc2[4][2];
    const uint64_t z2 = pack2(0.f);
    #pragma unroll
    for (int i = 0; i < 4; i++) { acc2[i][0] = z2; acc2[i][1] = z2; }

    const float* kpBase = g_kp + (size_t)bh * Nn * Mf + mtile*64;
    const float* vBase  = g_qkv + (size_t)b * Nn * QKVS + 2*Dm + h*DHe;

    for (int n0 = 0; n0 < Nn; n0 += 32) {
        #pragma unroll
        for (int it = 0; it < 8; it++) {
            int j = it*256 + tid;
            int nn = j >> 6, cq = j & 63;
            kpc[nn][cq] = kpBase[(size_t)(n0+nn)*Mf + cq];
            vc [nn][cq] = vBase [(size_t)(n0+nn)*QKVS + cq];
        }
        __syncthreads();
        #pragma unroll
        for (int nn = 0; nn < 32; nn++) {
            float4 kf = *(const float4*)&kpc[nn][ty*4];
            float4 vf = *(const float4*)&vc [nn][tx*4];
            uint64_t v01, v23;
            asm("mov.b64 %0, {%1, %2};" : "=l"(v01) : "f"(vf.x), "f"(vf.y));
            asm("mov.b64 %0, {%1, %2};" : "=l"(v23) : "f"(vf.z), "f"(vf.w));
            float kr[4] = {kf.x,kf.y,kf.z,kf.w};
            #pragma unroll
            for (int i = 0; i < 4; i++) {
                uint64_t kk = pack2(kr[i]);
                ffma2(acc2[i][0], kk, v01);
                ffma2(acc2[i][1], kk, v23);
            }
        }
        __syncthreads();
    }
    // write transposed half directly: ctxTh[bh][d][m]
    __half* dst = g_ctxTh + (size_t)bh*DHe*Mf;
    #pragma unroll
    for (int i = 0; i < 4; i++) {
        int m = mtile*64 + ty*4 + i;
        float2 lo = unpack2(acc2[i][0]);
        float2 hi = unpack2(acc2[i][1]);
        dst[(tx*4+0)*Mf + m] = __float2half_rn(lo.x);
        dst[(tx*4+1)*Mf + m] = __float2half_rn(lo.y);
        dst[(tx*4+2)*Mf + m] = __float2half_rn(hi.x);
        dst[(tx*4+3)*Mf + m] = __float2half_rn(hi.y);
    }
}

// ---------------- LayerNorm(a + b) * g + be ----------------
__global__ __launch_bounds__(256)
void ln_kernel(const float* __restrict__ A, const float* __restrict__ Bc,
               const float* __restrict__ g, const float* __restrict__ be,
               float* __restrict__ outf, __half* __restrict__ outh)
{
    __shared__ float s1s[8], s2s[8], bc[2];
    const int row = blockIdx.x;
    const int tid = threadIdx.x;
    const int lane = tid & 31, wid = tid >> 5;

    const float4* a4 = (const float4*)(A  + (size_t)row*Dm);
    const float4* b4 = (const float4*)(Bc + (size_t)row*Dm);
    float4 va = a4[tid], vb = b4[tid];
    float4 v = make_float4(va.x+vb.x, va.y+vb.y, va.z+vb.z, va.w+vb.w);

    float s1 = v.x+v.y+v.z+v.w;
    float s2 = v.x*v.x+v.y*v.y+v.z*v.z+v.w*v.w;
    #pragma unroll
    for (int off = 16; off; off >>= 1) {
        s1 += __shfl_xor_sync(0xffffffffu, s1, off);
        s2 += __shfl_xor_sync(0xffffffffu, s2, off);
    }
    if (lane == 0) { s1s[wid] = s1; s2s[wid] = s2; }
    __syncthreads();
    if (tid == 0) {
        float S1 = 0.f, S2 = 0.f;
        #pragma unroll
        for (int i = 0; i < 8; i++) { S1 += s1s[i]; S2 += s2s[i]; }
        float mu = S1 * (1.f/Dm);
        float var = S2 * (1.f/Dm) - mu*mu;
        bc[0] = mu;
        bc[1] = rsqrtf(var + LNEPS);
    }
    __syncthreads();
    float mu = bc[0], rstd = bc[1];

    float4 gg = ((const float4*)g)[tid];
    float4 bb = ((const float4*)be)[tid];
    float4 o = make_float4((v.x-mu)*rstd*gg.x + bb.x,
                           (v.y-mu)*rstd*gg.y + bb.y,
                           (v.z-mu)*rstd*gg.z + bb.z,
                           (v.w-mu)*rstd*gg.w + bb.w);
    ((float4*)(outf + (size_t)row*Dm))[tid] = o;
    if (outh) {
        __half2* oh = (__half2*)(outh + (size_t)row*Dm) + 2*tid;
        oh[0] = __floats2half2_rn(o.x, o.y);
        oh[1] = __floats2half2_rn(o.z, o.w);
    }
}

// ---------------- host ----------------
static inline void launch_hgemm(const __half* A, const __half* W, const float* bias,
                                float* Cf, __half* Ch, int M, int N, int K, int relu,
                                int mode, size_t zsA, size_t zsC, int gz)
{
    int gx = N / 128, gy = M / 256;
    int tiles = gx * gy * gz;
    int grid = tiles < GEMM_GRID ? tiles : GEMM_GRID;
    hgemm<<<grid, 256, HSMEM>>>(A, W, bias, Cf, Ch, M, N, K, relu, mode, zsA, zsC,
                                tiles, gx, gy);
}

extern "C" void kernel_launch(void* const* d_in, const int* in_sizes, int n_in,
                              void* d_out, int out_size)
{
    const float* video = (const float*)d_in[0];
    const float* Wq    = (const float*)d_in[1];
    const float* bq    = (const float*)d_in[2];
    const float* Wk    = (const float*)d_in[3];
    const float* bk    = (const float*)d_in[4];
    const float* Wv    = (const float*)d_in[5];
    const float* bv    = (const float*)d_in[6];
    const float* Wo    = (const float*)d_in[7];
    const float* bo    = (const float*)d_in[8];
    const float* proj  = (const float*)d_in[9];
    const float* W1    = (const float*)d_in[10];
    const float* b1    = (const float*)d_in[11];
    const float* W2    = (const float*)d_in[12];
    const float* b2    = (const float*)d_in[13];
    const float* g2    = (const float*)d_in[14];
    const float* be2   = (const float*)d_in[15];
    const float* g3    = (const float*)d_in[16];
    const float* be3   = (const float*)d_in[17];
    float* out = (float*)d_out;

    __half *vidh, *wqkvh, *woh, *w1h, *w2h, *attnh, *x1h, *ffh, *qh, *kh, *projh;
    float *bqkv, *qkv, *y, *x1, *qp, *kp, *zerob;
    cudaGetSymbolAddress((void**)&vidh,  g_vidh);
    cudaGetSymbolAddress((void**)&wqkvh, g_wqkvh);
    cudaGetSymbolAddress((void**)&bqkv,  g_bqkv);
    cudaGetSymbolAddress((void**)&woh,   g_woh);
    cudaGetSymbolAddress((void**)&w1h,   g_w1h);
    cudaGetSymbolAddress((void**)&w2h,   g_w2h);
    cudaGetSymbolAddress((void**)&qkv,   g_qkv);
    cudaGetSymbolAddress((void**)&attnh, g_attnh);
    cudaGetSymbolAddress((void**)&x1h,   g_x1h);
    cudaGetSymbolAddress((void**)&ffh,   g_ffh);
    cudaGetSymbolAddress((void**)&y,     g_y);
    cudaGetSymbolAddress((void**)&x1,    g_x1);
    cudaGetSymbolAddress((void**)&qh,    g_qh);
    cudaGetSymbolAddress((void**)&kh,    g_kh);
    cudaGetSymbolAddress((void**)&projh, g_projh);
    cudaGetSymbolAddress((void**)&qp,    g_qp);
    cudaGetSymbolAddress((void**)&kp,    g_kp);
    cudaGetSymbolAddress((void**)&zerob, g_zerob);

    cudaFuncSetAttribute(hgemm,     cudaFuncAttributeMaxDynamicSharedMemorySize, HSMEM);
    cudaFuncSetAttribute(hgemm_n64, cudaFuncAttributeMaxDynamicSharedMemorySize, N64SMEM);

    // 0. conversions
    pack_qkvh<<<(3*Dm*Dm + 255)/256, 256>>>(Wq, Wk, Wv, bq, bk, bv);
    pack_projh<<<(Mf*DHe + 255)/256, 256>>>(proj);
    f2h_kernel<<<(Tt*Dm/4 + 255)/256, 256>>>(video, vidh, Tt*Dm/4);
    f2h_kernel<<<(Dm*Dm/4 + 255)/256, 256>>>(Wo, woh, Dm*Dm/4);
    f2h_kernel<<<(DFFe*Dm/4 + 255)/256, 256>>>(W1, w1h, DFFe*Dm/4);
    f2h_kernel<<<(Dm*DFFe/4 + 255)/256, 256>>>(W2, w2h, Dm*DFFe/4);
    init_kstab<<<1, 64>>>();

    // 1. fused QKV projection (mode 1: v slice fp32 + qh/kh half + diag)
    launch_hgemm(vidh, wqkvh, bqkv, qkv, nullptr, Tt, QKVS, Dm, 0, 1, 0, 0, 1);

    // 2. feature-map GEMMs (batched per head); feat-k fuses kstab max (mode 2)
    launch_hgemm(qh, projh, zerob, qp, nullptr, Nn, Mf, DHe, 0, 0,
                 (size_t)Nn*DHe, (size_t)Nn*Mf, BH);
    launch_hgemm(kh, projh, zerob, kp, nullptr, Nn, Mf, DHe, 0, 2,
                 (size_t)Nn*DHe, (size_t)Nn*Mf, BH);

    // 3. exps (k exp fused with ksum partials)
    qexp_kernel<<<(BH*Nn)/8, 256>>>();
    kexp_ksum_kernel<<<dim3(BH, 16), 256>>>();
    ksum_reduce_kernel<<<BH, 256>>>();

    // 4. linear attention
    den_kernel<<<(BH*Nn)/8, 256>>>();
    ctx_kernel<<<dim3(BH, Mf/64), 256>>>();        // writes ctxTh directly
    hgemm_n64<<<dim3(Nn/256, BH), 256, N64SMEM>>>();

    // 5. output projection + residual LN
    launch_hgemm(attnh, woh, bo, y, nullptr, Tt, Dm, Dm, 0, 0, 0, 0, 1);
    ln_kernel<<<Tt, 256>>>(video, y, g2, be2, x1, x1h);

    // 6. FFN
    launch_hgemm(x1h, w1h, b1, nullptr, ffh, Tt, DFFe, Dm, 1, 0, 0, 0, 1);
    launch_hgemm(ffh, w2h, b2, y, nullptr, Tt, Dm, DFFe, 0, 0, 0, 0, 1);
    ln_kernel<<<Tt, 256>>>(x1, y, g3, be3, out, nullptr);
}

// round 16
// speedup vs baseline: 1.5013x; 1.0142x over previous
#include <cuda_runtime.h>
#include <cuda_fp16.h>
#include <math.h>
#include <stdint.h>

// ---------------- problem constants ----------------
#define Bb     4
#define Nn     4096
#define Dm     1024
#define Hh     16
#define DHe    64
#define DFFe   4096
#define Mf     256
#define BH     (Bb*Hh)          // 64
#define Tt     (Bb*Nn)          // 16384
#define QKVS   3072
#define NORMF  0.3535533905932738f   // 64^-0.25
#define RATIOF 0.0625f               // 256^-0.5
#define EPSKF  1e-4f
#define LNEPS  1e-5f
#define GEMM_GRID 296

// ---------------- scratch (device globals, no allocs) ----------------
__device__ __align__(256) __half g_vidh [Tt*Dm];
__device__ __align__(256) __half g_wqkvh[3*Dm*Dm];
__device__ float  g_bqkv[3*Dm];
__device__ __align__(256) __half g_woh  [Dm*Dm];
__device__ __align__(256) __half g_w1h  [DFFe*Dm];
__device__ __align__(256) __half g_w2h  [Dm*DFFe];
__device__ float  g_qkv [Tt*QKVS];    // fused q|k|v fp32 (only v slice written/read)
__device__ __align__(256) __half g_qh  [BH*Nn*DHe];
__device__ __align__(256) __half g_kh  [BH*Nn*DHe];
__device__ __align__(256) __half g_projh[Mf*DHe];
__device__ __align__(256) __half g_attnh[Tt*Dm];
__device__ __align__(256) __half g_x1h [Tt*Dm];
__device__ __align__(256) __half g_ffh [Tt*DFFe];
__device__ float  g_qp  [BH*Nn*Mf];
__device__ float  g_kp  [BH*Nn*Mf];
__device__ __align__(256) __half g_qph [BH*Nn*Mf];
__device__ float  g_qdiag[BH*Nn];
__device__ float  g_kdiag[BH*Nn];
__device__ float  g_kstab[BH];
__device__ float  g_ksum[BH*Mf];
__device__ float  g_ksum_part[16*BH*Mf];
__device__ float  g_den [BH*Nn];
__device__ __align__(256) __half g_ctxTh[BH*DHe*Mf];  // ctx^T half [bh][d][m]
__device__ float  g_y   [Tt*Dm];
__device__ float  g_x1  [Tt*Dm];
__device__ float  g_zerob[Mf];

// ---------------- PTX helpers ----------------
__device__ __forceinline__ uint32_t smem_u32(const void* p){
    uint32_t a;
    asm("{ .reg .u64 t; cvta.to.shared.u64 t, %1; cvt.u32.u64 %0, t; }" : "=r"(a) : "l"(p));
    return a;
}
#define CP_ASYNC16(dst, src) \
    asm volatile("cp.async.cg.shared.global [%0], [%1], 16;" :: "r"(dst), "l"(src))
#define CP_COMMIT() asm volatile("cp.async.commit_group;" ::: "memory")
#define CP_WAIT1()  asm volatile("cp.async.wait_group 1;" ::: "memory")
#define CP_WAIT0()  asm volatile("cp.async.wait_group 0;" ::: "memory")

__device__ __forceinline__ void mma_h(float c[4], const uint32_t a[4], const uint32_t b[2]){
    asm volatile("mma.sync.aligned.m16n8k16.row.col.f32.f16.f16.f32 "
        "{%0,%1,%2,%3}, {%4,%5,%6,%7}, {%8,%9}, {%0,%1,%2,%3};"
        : "+f"(c[0]), "+f"(c[1]), "+f"(c[2]), "+f"(c[3])
        : "r"(a[0]), "r"(a[1]), "r"(a[2]), "r"(a[3]), "r"(b[0]), "r"(b[1]));
}
__device__ __forceinline__ void atomicMaxF(float* addr, float v) {
    int old = __float_as_int(*addr);
    while (__int_as_float(old) < v) {
        int assumed = old;
        old = atomicCAS((int*)addr, assumed, __float_as_int(v));
        if (old == assumed) break;
    }
}
__device__ __forceinline__ uint64_t pack2(float x){
    uint64_t r; asm("mov.b64 %0, {%1, %1};" : "=l"(r) : "f"(x)); return r;
}
__device__ __forceinline__ void ffma2(uint64_t& c, uint64_t a, uint64_t b){
    asm("fma.rn.f32x2 %0, %1, %2, %0;" : "+l"(c) : "l"(a), "l"(b));
}
__device__ __forceinline__ float2 unpack2(uint64_t v){
    float lo, hi; asm("mov.b64 {%0, %1}, %2;" : "=f"(lo), "=f"(hi) : "l"(v));
    return make_float2(lo, hi);
}

// ---------------- conversion kernels ----------------
__global__ __launch_bounds__(256)
void f2h_kernel(const float* __restrict__ src, __half* __restrict__ dst, int n4)
{
    int i = blockIdx.x*256 + threadIdx.x;
    if (i < n4) {
        float4 v = ((const float4*)src)[i];
        __half2* d = (__half2*)dst + 2*i;
        d[0] = __floats2half2_rn(v.x, v.y);
        d[1] = __floats2half2_rn(v.z, v.w);
    }
}
__global__ __launch_bounds__(256)
void pack_qkvh(const float* __restrict__ Wq, const float* __restrict__ Wk,
               const float* __restrict__ Wv, const float* __restrict__ bq,
               const float* __restrict__ bk, const float* __restrict__ bv)
{
    size_t i = (size_t)blockIdx.x*256 + threadIdx.x;
    if (i < (size_t)3*Dm*Dm) {
        int seg = (int)(i >> 20);
        size_t off = i & 0xFFFFF;
        const float* s = (seg == 0) ? Wq : (seg == 1) ? Wk : Wv;
        g_wqkvh[i] = __float2half_rn(s[off]);
    }
    if (i < 3*Dm)
        g_bqkv[i] = (i < Dm) ? bq[i] : (i < 2*Dm) ? bk[i-Dm] : bv[i-2*Dm];
}
__global__ __launch_bounds__(256)
void pack_projh(const float* __restrict__ proj)
{
    int i = blockIdx.x*256 + threadIdx.x;
    if (i < Mf*DHe) g_projh[i] = __float2half_rn(proj[i] * NORMF);
}

// ---------------- fp16 mma GEMM-NT, persistent tiles (R15 base) ------------
#define HSTR    72
#define HA_BY   (256*HSTR*2)
#define HB_BY   (128*HSTR*2)
#define HSTAGE  (HA_BY+HB_BY)
#define HSMEM   (2*HSTAGE)       // 110592

__global__ __launch_bounds__(256)
void hgemm(const __half* __restrict__ A, const __half* __restrict__ W,
           const float* __restrict__ bias, float* __restrict__ Cf,
           __half* __restrict__ Ch, int M, int N, int K, int relu,
           int mode, size_t zsA, size_t zsC, int tiles, int gx, int gy)
{
    extern __shared__ char smc[];
    const uint32_t sb = smem_u32(smc);
    const int tid  = threadIdx.x;
    const int lane = tid & 31;
    const int w    = tid >> 5;
    const int wm   = (w & 3) * 64;
    const int wn   = (w >> 2) * 64;
    const int lr   = lane >> 2;
    const int lc   = lane & 3;
    const int r8 = tid >> 3, cc8 = tid & 7;
    const int KT = K / 64;

    for (int t = blockIdx.x; t < tiles; t += gridDim.x) {
        const int bx = t % gx;
        const int rr = t / gx;
        const int by = rr % gy;
        const int bz = rr / gy;

        const __half* At = A + (size_t)bz * zsA;
        float* Cft = Cf ? Cf + (size_t)bz * zsC : (float*)0;
        __half* Cht = Ch ? Ch + (size_t)bz * zsC : (__half*)0;

        const int blockM = by * 256;
        const int blockN = bx * 128;

        float c[4][8][4];
        #pragma unroll
        for (int i = 0; i < 4; i++)
            #pragma unroll
            for (int j = 0; j < 8; j++)
                #pragma unroll
                for (int tt = 0; tt < 4; tt++) c[i][j][tt] = 0.f;

        const __half* Abase = At + (size_t)blockM * K;
        const __half* Wbase = W + (size_t)blockN * K;

        auto issue = [&](int kt) {
            const int buf = kt & 1;
            const uint32_t dA = sb + buf*HSTAGE;
            const uint32_t dB = dA + HA_BY;
            const __half* As = Abase + kt*64;
            const __half* Ws = Wbase + kt*64;
            #pragma unroll
            for (int it = 0; it < 8; it++) {
                int r = r8 + it*32;
                CP_ASYNC16(dA + r*(HSTR*2) + cc8*16, As + (size_t)r*K + cc8*8);
            }
            #pragma unroll
            for (int it = 0; it < 4; it++) {
                int r = r8 + it*32;
                CP_ASYNC16(dB + r*(HSTR*2) + cc8*16, Ws + (size_t)r*K + cc8*8);
            }
        };

        issue(0); CP_COMMIT();
        if (KT > 1) { issue(1); CP_COMMIT(); CP_WAIT1(); }
        else        { CP_WAIT0(); }
        __syncthreads();

        for (int kt = 0; kt < KT; kt++) {
            const char* bufA = smc + (kt & 1)*HSTAGE;
            const char* bufB = bufA + HA_BY;

            #pragma unroll
            for (int ks = 0; ks < 4; ks++) {
                const int k0 = ks*16;
                uint32_t a[4][4], b[8][2];
                #pragma unroll
                for (int i = 0; i < 4; i++) {
                    int r = wm + i*16 + lr;
                    const char* p = bufA + (r*HSTR + k0 + lc*2)*2;
                    a[i][0] = *(const uint32_t*)(p);
                    a[i][1] = *(const uint32_t*)(p + 8*HSTR*2);
                    a[i][2] = *(const uint32_t*)(p + 16);
                    a[i][3] = *(const uint32_t*)(p + 8*HSTR*2 + 16);
                }
                #pragma unroll
                for (int j = 0; j < 8; j++) {
                    int n = wn + j*8 + lr;
                    const char* p = bufB + (n*HSTR + k0 + lc*2)*2;
                    b[j][0] = *(const uint32_t*)(p);
                    b[j][1] = *(const uint32_t*)(p + 16);
                }
                #pragma unroll
                for (int i = 0; i < 4; i++)
                    #pragma unroll
                    for (int j = 0; j < 8; j++)
                        mma_h(c[i][j], a[i], b[j]);
            }
            __syncthreads();
            if (kt + 2 < KT) {
                issue(kt + 2); CP_COMMIT();
                CP_WAIT1(); __syncthreads();
            } else if (kt + 1 < KT) {
                CP_WAIT0(); __syncthreads();
            }
        }
        __syncthreads();   // protect smem before next tile's prologue

        // ---- epilogue (R15: dead q/k fp32 stores skipped) ----
        int seg = 3, hh = 0;
        if (mode == 1) { int slot = (blockN + wn) >> 6; seg = slot >> 4; hh = slot & 15; }
        const bool storeF = (Cft != 0) && (mode != 1 || seg == 2);
        float wmax = -INFINITY;

        #pragma unroll
        for (int i = 0; i < 4; i++) {
            int gr = blockM + wm + i*16 + lr;
            float ds0 = 0.f, ds1 = 0.f;
            #pragma unroll
            for (int j = 0; j < 8; j++) {
                int gc = blockN + wn + j*8 + 2*lc;
                float b0 = bias[gc], b1 = bias[gc+1];
                float o0 = c[i][j][0] + b0, o1 = c[i][j][1] + b1;
                float o2 = c[i][j][2] + b0, o3 = c[i][j][3] + b1;
                if (relu) {
                    o0 = fmaxf(o0, 0.f); o1 = fmaxf(o1, 0.f);
                    o2 = fmaxf(o2, 0.f); o3 = fmaxf(o3, 0.f);
                }
                if (mode == 2)
                    wmax = fmaxf(wmax, fmaxf(fmaxf(o0, o1), fmaxf(o2, o3)));
                if (storeF) {
                    *(float2*)(Cft + (size_t)gr*N + gc)     = make_float2(o0, o1);
                    *(float2*)(Cft + (size_t)(gr+8)*N + gc) = make_float2(o2, o3);
                } else if (Cht) {
                    *(__half2*)(Cht + (size_t)gr*N + gc)     = __floats2half2_rn(o0, o1);
                    *(__half2*)(Cht + (size_t)(gr+8)*N + gc) = __floats2half2_rn(o2, o3);
                }
                if (mode == 1 && seg < 2) {
                    int d = gc & 63, bb = gr >> 12, nn = gr & 4095;
                    size_t hidx = ((size_t)((bb<<4) + hh)*4096 + nn)*64 + d;
                    __half* dst = (seg == 0) ? g_qh : g_kh;
                    *(__half2*)(dst + hidx)          = __floats2half2_rn(o0, o1);
                    *(__half2*)(dst + hidx + 8*64)   = __floats2half2_rn(o2, o3);
                    ds0 += o0*o0 + o1*o1;
                    ds1 += o2*o2 + o3*o3;
                }
            }
            if (mode == 1 && seg < 2) {
                ds0 += __shfl_xor_sync(0xffffffffu, ds0, 1);
                ds0 += __shfl_xor_sync(0xffffffffu, ds0, 2);
                ds1 += __shfl_xor_sync(0xffffffffu, ds1, 1);
                ds1 += __shfl_xor_sync(0xffffffffu, ds1, 2);
                if (lc == 0) {
                    int bb = gr >> 12, nn = gr & 4095;
                    size_t r0 = (size_t)((bb<<4) + hh)*4096 + nn;
                    float* dd = (seg == 0) ? g_qdiag : g_kdiag;
                    dd[r0]     = 0.0625f * ds0;
                    dd[r0 + 8] = 0.0625f * ds1;
                }
            }
        }
        if (mode == 2) {
            #pragma unroll
            for (int off = 16; off; off >>= 1)
                wmax = fmaxf(wmax, __shfl_xor_sync(0xffffffffu, wmax, off));
            if (lane == 0) atomicMaxF(&g_kstab[bz], wmax);
        }
    }
}

// ---------------- attnout GEMM: per head M=4096 N=64 K=256 ----------------
#define N64_HA  (256*HSTR*2)
#define N64_HB  (64*HSTR*2)
#define N64_ST  (N64_HA+N64_HB)
#define N64SMEM (2*N64_ST)

__global__ __launch_bounds__(256)
void hgemm_n64()
{
    extern __shared__ char smc[];
    const uint32_t sb = smem_u32(smc);
    const int tid  = threadIdx.x;
    const int lane = tid & 31;
    const int w    = tid >> 5;
    const int wm   = (w & 3) * 64;
    const int wn   = (w >> 2) * 32;
    const int lr   = lane >> 2;
    const int lc   = lane & 3;

    const int bh     = blockIdx.y;
    const int blockM = blockIdx.x * 256;
    const __half* A = g_qph  + (size_t)bh*Nn*Mf + (size_t)blockM*Mf;
    const __half* B = g_ctxTh + (size_t)bh*DHe*Mf;

    float c[4][4][4];
    #pragma unroll
    for (int i = 0; i < 4; i++)
        #pragma unroll
        for (int j = 0; j < 4; j++)
            #pragma unroll
            for (int t = 0; t < 4; t++) c[i][j][t] = 0.f;

    const int r8 = tid >> 3, cc8 = tid & 7;

    auto issue = [&](int kt) {
        const int buf = kt & 1;
        const uint32_t dA = sb + buf*N64_ST;
        const uint32_t dB = dA + N64_HA;
        const __half* As = A + kt*64;
        const __half* Bs = B + kt*64;
        #pragma unroll
        for (int it = 0; it < 8; it++) {
            int r = r8 + it*32;
            CP_ASYNC16(dA + r*(HSTR*2) + cc8*16, As + (size_t)r*Mf + cc8*8);
        }
        #pragma unroll
        for (int it = 0; it < 2; it++) {
            int r = r8 + it*32;
            CP_ASYNC16(dB + r*(HSTR*2) + cc8*16, Bs + (size_t)r*Mf + cc8*8);
        }
    };

    issue(0); CP_COMMIT();
    issue(1); CP_COMMIT();
    CP_WAIT1(); __syncthreads();

    const int KT = Mf/64;   // 4
    for (int kt = 0; kt < KT; kt++) {
        const char* bufA = smc + (kt & 1)*N64_ST;
        const char* bufB = bufA + N64_HA;

        #pragma unroll
        for (int ks = 0; ks < 4; ks++) {
            const int k0 = ks*16;
            uint32_t a[4][4], b[4][2];
            #pragma unroll
            for (int i = 0; i < 4; i++) {
                int r = wm + i*16 + lr;
                const char* p = bufA + (r*HSTR + k0 + lc*2)*2;
                a[i][0] = *(const uint32_t*)(p);
                a[i][1] = *(const uint32_t*)(p + 8*HSTR*2);
                a[i][2] = *(const uint32_t*)(p + 16);
                a[i][3] = *(const uint32_t*)(p + 8*HSTR*2 + 16);
            }
            #pragma unroll
            for (int j = 0; j < 4; j++) {
                int n = wn + j*8 + lr;
                const char* p = bufB + (n*HSTR + k0 + lc*2)*2;
                b[j][0] = *(const uint32_t*)(p);
                b[j][1] = *(const uint32_t*)(p + 16);
            }
            #pragma unroll
            for (int i = 0; i < 4; i++)
                #pragma unroll
                for (int j = 0; j < 4; j++)
                    mma_h(c[i][j], a[i], b[j]);
        }
        __syncthreads();
        if (kt + 2 < KT) {
            issue(kt + 2); CP_COMMIT();
            CP_WAIT1(); __syncthreads();
        } else if (kt + 1 < KT) {
            CP_WAIT0(); __syncthreads();
        }
    }

    const int bb = bh >> 4, h = bh & 15;
    #pragma unroll
    for (int i = 0; i < 4; i++) {
        int n0 = blockM + wm + i*16 + lr;
        float rd0 = 1.f / g_den[bh*Nn + n0];
        float rd1 = 1.f / g_den[bh*Nn + n0 + 8];
        size_t t0 = ((size_t)bb*Nn + n0)*Dm + h*64;
        size_t t1 = t0 + (size_t)8*Dm;
        #pragma unroll
        for (int j = 0; j < 4; j++) {
            int d = wn + j*8 + 2*lc;
            *(__half2*)(g_attnh + t0 + d) = __floats2half2_rn(c[i][j][0]*rd0, c[i][j][1]*rd0);
            *(__half2*)(g_attnh + t1 + d) = __floats2half2_rn(c[i][j][2]*rd1, c[i][j][3]*rd1);
        }
    }
}

// ---------------- init kstab ----------------
__global__ void init_kstab() {
    if (threadIdx.x < BH) g_kstab[threadIdx.x] = -INFINITY;
}

// ---------------- fused qexp + den (runs after ksum_reduce) ----------------
// warp per row: rowmax, exp -> qph half, then den = (half-rounded qp).ksum
__global__ __launch_bounds__(256)
void qexp_den_kernel()
{
    const int row = blockIdx.x*8 + (threadIdx.x >> 5);
    const int lane = threadIdx.x & 31;
    const int bh = row >> 12;
    const float4* xp4 = (const float4*)(g_qp + (size_t)row*Mf);
    float4 v0 = xp4[lane], v1 = xp4[lane+32];
    float mx = fmaxf(fmaxf(fmaxf(v0.x,v0.y),fmaxf(v0.z,v0.w)),
                     fmaxf(fmaxf(v1.x,v1.y),fmaxf(v1.z,v1.w)));
    #pragma unroll
    for (int off = 16; off; off >>= 1)
        mx = fmaxf(mx, __shfl_xor_sync(0xffffffffu, mx, off));
    float sh = g_qdiag[row] + mx;

    __half2 h0 = __floats2half2_rn(__expf(v0.x-sh)+EPSKF, __expf(v0.y-sh)+EPSKF);
    __half2 h1 = __floats2half2_rn(__expf(v0.z-sh)+EPSKF, __expf(v0.w-sh)+EPSKF);
    __half2 h2 = __floats2half2_rn(__expf(v1.x-sh)+EPSKF, __expf(v1.y-sh)+EPSKF);
    __half2 h3 = __floats2half2_rn(__expf(v1.z-sh)+EPSKF, __expf(v1.w-sh)+EPSKF);

    __half2* o = (__half2*)(g_qph + (size_t)row*Mf);
    o[2*lane]    = h0;
    o[2*lane+1]  = h1;
    o[2*lane+64] = h2;
    o[2*lane+65] = h3;

    // den: identical math to the old den_kernel (half-rounded qp dot ksum).
    // lane holds m = {8*lane..8*lane+3, 8*lane+256.. } -> matches ksum indices:
    // old kernel had lane owning qph[8*lane..8*lane+7] with ks4[2*lane],[2*lane+1].
    // Here lane owns m = 4*lane..4*lane+3 (from v0) and 128+4*lane.. (from v1);
    // load matching ksum chunks.
    const float4* ks4 = (const float4*)(g_ksum + bh*Mf);
    float4 k0 = ks4[lane], k1 = ks4[lane+32];
    float2 q0 = __half22float2(h0);
    float2 q1 = __half22float2(h1);
    float2 q2 = __half22float2(h2);
    float2 q3 = __half22float2(h3);
    float s = q0.x*k0.x + q0.y*k0.y + q1.x*k0.z + q1.y*k0.w
            + q2.x*k1.x + q2.y*k1.y + q3.x*k1.z + q3.y*k1.w;
    #pragma unroll
    for (int off = 16; off; off >>= 1) s += __shfl_xor_sync(0xffffffffu, s, off);
    if (lane == 0) g_den[row] = s;
}

// ---------------- fused kexp + ksum partials ----------------
__global__ __launch_bounds__(256)
void kexp_ksum_kernel()
{
    const int bh = blockIdx.x;
    const int part = blockIdx.y;
    const int m = threadIdx.x;
    const float stab = g_kstab[bh];
    const int row0 = bh*Nn + part*256;
    float* kp = g_kp + (size_t)bh * Nn * Mf + (size_t)part * 256 * Mf + m;
    float acc = 0.f;
    #pragma unroll 4
    for (int n = 0; n < 256; n++) {
        float xp = kp[(size_t)n * Mf];
        float kv = RATIOF * (__expf(xp - g_kdiag[row0 + n] - stab) + EPSKF);
        kp[(size_t)n * Mf] = kv;
        acc += kv;
    }
    g_ksum_part[(part*BH + bh)*Mf + m] = acc;
}
__global__ __launch_bounds__(256)
void ksum_reduce_kernel()
{
    const int bh = blockIdx.x;
    const int m = threadIdx.x;
    float acc = 0.f;
    #pragma unroll
    for (int p = 0; p < 16; p++) acc += g_ksum_part[(p*BH + bh)*Mf + m];
    g_ksum[bh*Mf + m] = acc;
}

// ---------------- ctx (packed f32x2 FFMA2), writes ctx^T half directly ----
__global__ __launch_bounds__(256)
void ctx_kernel()
{
    __shared__ float kpc[32][64];
    __shared__ float vc [32][64];

    const int bh = blockIdx.x;
    const int mtile = blockIdx.y;
    const int b = bh >> 4, h = bh & 15;
    const int tid = threadIdx.x;
    const int tx = tid & 15;
    const int ty = tid >> 4;

    uint64_t acc2[4][2];
    const uint64_t z2 = pack2(0.f);
    #pragma unroll
    for (int i = 0; i < 4; i++) { acc2[i][0] = z2; acc2[i][1] = z2; }

    const float* kpBase = g_kp + (size_t)bh * Nn * Mf + mtile*64;
    const float* vBase  = g_qkv + (size_t)b * Nn * QKVS + 2*Dm + h*DHe;

    for (int n0 = 0; n0 < Nn; n0 += 32) {
        #pragma unroll
        for (int it = 0; it < 8; it++) {
            int j = it*256 + tid;
            int nn = j >> 6, cq = j & 63;
            kpc[nn][cq] = kpBase[(size_t)(n0+nn)*Mf + cq];
            vc [nn][cq] = vBase [(size_t)(n0+nn)*QKVS + cq];
        }
        __syncthreads();
        #pragma unroll
        for (int nn = 0; nn < 32; nn++) {
            float4 kf = *(const float4*)&kpc[nn][ty*4];
            float4 vf = *(const float4*)&vc [nn][tx*4];
            uint64_t v01, v23;
            asm("mov.b64 %0, {%1, %2};" : "=l"(v01) : "f"(vf.x), "f"(vf.y));
            asm("mov.b64 %0, {%1, %2};" : "=l"(v23) : "f"(vf.z), "f"(vf.w));
            float kr[4] = {kf.x,kf.y,kf.z,kf.w};
            #pragma unroll
            for (int i = 0; i < 4; i++) {
                uint64_t kk = pack2(kr[i]);
                ffma2(acc2[i][0], kk, v01);
                ffma2(acc2[i][1], kk, v23);
            }
        }
        __syncthreads();
    }
    // write transposed half directly: ctxTh[bh][d][m]
    __half* dst = g_ctxTh + (size_t)bh*DHe*Mf;
    #pragma unroll
    for (int i = 0; i < 4; i++) {
        int m = mtile*64 + ty*4 + i;
        float2 lo = unpack2(acc2[i][0]);
        float2 hi = unpack2(acc2[i][1]);
        dst[(tx*4+0)*Mf + m] = __float2half_rn(lo.x);
        dst[(tx*4+1)*Mf + m] = __float2half_rn(lo.y);
        dst[(tx*4+2)*Mf + m] = __float2half_rn(hi.x);
        dst[(tx*4+3)*Mf + m] = __float2half_rn(hi.y);
    }
}

// ---------------- LayerNorm(a + b) * g + be ----------------
__global__ __launch_bounds__(256)
void ln_kernel(const float* __restrict__ A, const float* __restrict__ Bc,
               const float* __restrict__ g, const float* __restrict__ be,
               float* __restrict__ outf, __half* __restrict__ outh)
{
    __shared__ float s1s[8], s2s[8], bc[2];
    const int row = blockIdx.x;
    const int tid = threadIdx.x;
    const int lane = tid & 31, wid = tid >> 5;

    const float4* a4 = (const float4*)(A  + (size_t)row*Dm);
    const float4* b4 = (const float4*)(Bc + (size_t)row*Dm);
    float4 va = a4[tid], vb = b4[tid];
    float4 v = make_float4(va.x+vb.x, va.y+vb.y, va.z+vb.z, va.w+vb.w);

    float s1 = v.x+v.y+v.z+v.w;
    float s2 = v.x*v.x+v.y*v.y+v.z*v.z+v.w*v.w;
    #pragma unroll
    for (int off = 16; off; off >>= 1) {
        s1 += __shfl_xor_sync(0xffffffffu, s1, off);
        s2 += __shfl_xor_sync(0xffffffffu, s2, off);
    }
    if (lane == 0) { s1s[wid] = s1; s2s[wid] = s2; }
    __syncthreads();
    if (tid == 0) {
        float S1 = 0.f, S2 = 0.f;
        #pragma unroll
        for (int i = 0; i < 8; i++) { S1 += s1s[i]; S2 += s2s[i]; }
        float mu = S1 * (1.f/Dm);
        float var = S2 * (1.f/Dm) - mu*mu;
        bc[0] = mu;
        bc[1] = rsqrtf(var + LNEPS);
    }
    __syncthreads();
    float mu = bc[0], rstd = bc[1];

    float4 gg = ((const float4*)g)[tid];
    float4 bb = ((const float4*)be)[tid];
    float4 o = make_float4((v.x-mu)*rstd*gg.x + bb.x,
                           (v.y-mu)*rstd*gg.y + bb.y,
                           (v.z-mu)*rstd*gg.z + bb.z,
                           (v.w-mu)*rstd*gg.w + bb.w);
    ((float4*)(outf + (size_t)row*Dm))[tid] = o;
    if (outh) {
        __half2* oh = (__half2*)(outh + (size_t)row*Dm) + 2*tid;
        oh[0] = __floats2half2_rn(o.x, o.y);
        oh[1] = __floats2half2_rn(o.z, o.w);
    }
}

// ---------------- host ----------------
static inline void launch_hgemm(const __half* A, const __half* W, const float* bias,
                                float* Cf, __half* Ch, int M, int N, int K, int relu,
                                int mode, size_t zsA, size_t zsC, int gz)
{
    int gx = N / 128, gy = M / 256;
    int tiles = gx * gy * gz;
    int grid = tiles < GEMM_GRID ? tiles : GEMM_GRID;
    hgemm<<<grid, 256, HSMEM>>>(A, W, bias, Cf, Ch, M, N, K, relu, mode, zsA, zsC,
                                tiles, gx, gy);
}

extern "C" void kernel_launch(void* const* d_in, const int* in_sizes, int n_in,
                              void* d_out, int out_size)
{
    const float* video = (const float*)d_in[0];
    const float* Wq    = (const float*)d_in[1];
    const float* bq    = (const float*)d_in[2];
    const float* Wk    = (const float*)d_in[3];
    const float* bk    = (const float*)d_in[4];
    const float* Wv    = (const float*)d_in[5];
    const float* bv    = (const float*)d_in[6];
    const float* Wo    = (const float*)d_in[7];
    const float* bo    = (const float*)d_in[8];
    const float* proj  = (const float*)d_in[9];
    const float* W1    = (const float*)d_in[10];
    const float* b1    = (const float*)d_in[11];
    const float* W2    = (const float*)d_in[12];
    const float* b2    = (const float*)d_in[13];
    const float* g2    = (const float*)d_in[14];
    const float* be2   = (const float*)d_in[15];
    const float* g3    = (const float*)d_in[16];
    const float* be3   = (const float*)d_in[17];
    float* out = (float*)d_out;

    __half *vidh, *wqkvh, *woh, *w1h, *w2h, *attnh, *x1h, *ffh, *qh, *kh, *projh;
    float *bqkv, *qkv, *y, *x1, *qp, *kp, *zerob;
    cudaGetSymbolAddress((void**)&vidh,  g_vidh);
    cudaGetSymbolAddress((void**)&wqkvh, g_wqkvh);
    cudaGetSymbolAddress((void**)&bqkv,  g_bqkv);
    cudaGetSymbolAddress((void**)&woh,   g_woh);
    cudaGetSymbolAddress((void**)&w1h,   g_w1h);
    cudaGetSymbolAddress((void**)&w2h,   g_w2h);
    cudaGetSymbolAddress((void**)&qkv,   g_qkv);
    cudaGetSymbolAddress((void**)&attnh, g_attnh);
    cudaGetSymbolAddress((void**)&x1h,   g_x1h);
    cudaGetSymbolAddress((void**)&ffh,   g_ffh);
    cudaGetSymbolAddress((void**)&y,     g_y);
    cudaGetSymbolAddress((void**)&x1,    g_x1);
    cudaGetSymbolAddress((void**)&qh,    g_qh);
    cudaGetSymbolAddress((void**)&kh,    g_kh);
    cudaGetSymbolAddress((void**)&projh, g_projh);
    cudaGetSymbolAddress((void**)&qp,    g_qp);
    cudaGetSymbolAddress((void**)&kp,    g_kp);
    cudaGetSymbolAddress((void**)&zerob, g_zerob);

    cudaFuncSetAttribute(hgemm,     cudaFuncAttributeMaxDynamicSharedMemorySize, HSMEM);
    cudaFuncSetAttribute(hgemm_n64, cudaFuncAttributeMaxDynamicSharedMemorySize, N64SMEM);

    // 0. conversions
    pack_qkvh<<<(3*Dm*Dm + 255)/256, 256>>>(Wq, Wk, Wv, bq, bk, bv);
    pack_projh<<<(Mf*DHe + 255)/256, 256>>>(proj);
    f2h_kernel<<<(Tt*Dm/4 + 255)/256, 256>>>(video, vidh, Tt*Dm/4);
    f2h_kernel<<<(Dm*Dm/4 + 255)/256, 256>>>(Wo, woh, Dm*Dm/4);
    f2h_kernel<<<(DFFe*Dm/4 + 255)/256, 256>>>(W1, w1h, DFFe*Dm/4);
    f2h_kernel<<<(Dm*DFFe/4 + 255)/256, 256>>>(W2, w2h, Dm*DFFe/4);
    init_kstab<<<1, 64>>>();

    // 1. fused QKV projection (mode 1: v slice fp32 + qh/kh half + diag)
    launch_hgemm(vidh, wqkvh, bqkv, qkv, nullptr, Tt, QKVS, Dm, 0, 1, 0, 0, 1);

    // 2. feature-map GEMMs (batched per head); feat-k fuses kstab max (mode 2)
    launch_hgemm(qh, projh, zerob, qp, nullptr, Nn, Mf, DHe, 0, 0,
                 (size_t)Nn*DHe, (size_t)Nn*Mf, BH);
    launch_hgemm(kh, projh, zerob, kp, nullptr, Nn, Mf, DHe, 0, 2,
                 (size_t)Nn*DHe, (size_t)Nn*Mf, BH);

    // 3. k exp fused with ksum partials, then reduce
    kexp_ksum_kernel<<<dim3(BH, 16), 256>>>();
    ksum_reduce_kernel<<<BH, 256>>>();

    // 4. fused q exp + den (needs ksum), then linear attention
    qexp_den_kernel<<<(BH*Nn)/8, 256>>>();
    ctx_kernel<<<dim3(BH, Mf/64), 256>>>();        // writes ctxTh directly
    hgemm_n64<<<dim3(Nn/256, BH), 256, N64SMEM>>>();

    // 5. output projection + residual LN
    launch_hgemm(attnh, woh, bo, y, nullptr, Tt, Dm, Dm, 0, 0, 0, 0, 1);
    ln_kernel<<<Tt, 256>>>(video, y, g2, be2, x1, x1h);

    // 6. FFN
    launch_hgemm(x1h, w1h, b1, nullptr, ffh, Tt, DFFe, Dm, 1, 0, 0, 0, 1);
    launch_hgemm(ffh, w2h, b2, y, nullptr, Tt, Dm, DFFe, 0, 0, 0, 0, 1);
    ln_kernel<<<Tt, 256>>>(x1, y, g3, be3, out, nullptr);
}